// round 12
// baseline (speedup 1.0000x reference)
#include <cuda_runtime.h>
#include <math.h>
#include <float.h>

#define G 8
#define NC (G*G*G)
#define MAXN 10016
#define MAXM 32768
#define KNN 16
#define NF 32
#define CAPW 512
#define WMAX 1024
#define NBKT 32
#define KD 8                // per-lane top-K depth (8 lanes/query)
#define IDXMASK 0x1FFu
#define CDMAX 0.1055f
#define BWIDTH (CDMAX / (float)NBKT)
#define INVBW ((float)NBKT / CDMAX)

// ---- device scratch (allocation-free) ----
__device__ float4 g_sorted[MAXN];
__device__ float4 g_icov_s[MAXN];
__device__ int g_cnt[NC], g_start[NC + 1];
__device__ int g_qcnt[NC], g_qstart[NC + 1];
__device__ int g_gcell[MAXN], g_grank[MAXN];
__device__ int g_qcell[MAXM], g_qrank[MAXM];
__device__ int g_qorder[MAXM];
__device__ int g_bar[4];                  // grid barriers + done ctr (self-reset)
__device__ float4 g_winpos[NC * CAPW + 32];
__device__ float4 g_winic[NC * CAPW + 32];
__device__ float  g_wincd[NC * CAPW + 32];
__device__ float  g_wmargin[NC];
__device__ int    g_nsw[NC];
__device__ int    g_nswp[NC];

__device__ __forceinline__ int cell_coord(float v) {
    int c = (int)(v * (float)G);
    return min(G - 1, max(0, c));
}

// 512-entry exclusive scan with 256 threads (2 entries/thread); zeroes src.
__device__ void scan512_zero(int* src, int* dst) {
    __shared__ int ws[8];
    int t = threadIdx.x, lane = t & 31, w = t >> 5;
    int c0 = src[2 * t], c1 = src[2 * t + 1];
    src[2 * t] = 0; src[2 * t + 1] = 0;
    int s = c0 + c1;
    int v = s;
    for (int o = 1; o < 32; o <<= 1) {
        int u = __shfl_up_sync(0xffffffffu, v, o);
        if (lane >= o) v += u;
    }
    if (lane == 31) ws[w] = v;
    __syncthreads();
    if (t < 32) {
        int p = (t < 8) ? ws[t] : 0;
        for (int o = 1; o < 8; o <<= 1) {
            int u = __shfl_up_sync(0xffffffffu, p, o);
            if (t >= o) p += u;
        }
        if (t < 8) ws[t] = p;
    }
    __syncthreads();
    int incl = v + (w ? ws[w - 1] : 0);
    int excl = incl - s;
    dst[2 * t + 1] = excl + c0;
    dst[2 * t + 2] = incl;
    if (t == 0) dst[0] = 0;
    __syncthreads();
}

// Grid barrier: all NC blocks co-resident (guaranteed by launch_bounds(256,4):
// 4 blocks/SM x 148 SMs = 592 >= 512). gpu-scope fences flush L1D.
__device__ __forceinline__ void grid_bar(int idx) {
    __threadfence();
    __syncthreads();
    if (threadIdx.x == 0) {
        atomicAdd(&g_bar[idx], 1);
        while (atomicAdd(&g_bar[idx], 0) < NC) __nanosleep(64);
    }
    __syncthreads();
    __threadfence();
}

// Fused prep: hist -> scan -> scatter -> per-cell radial window. One launch.
__global__ __launch_bounds__(256, 4)
void k_prep(const float* __restrict__ coords,
            const float* __restrict__ means,
            const float* __restrict__ logc, int N, int M) {
    __shared__ float4 spos4[WMAX];
    __shared__ float  skey[WMAX];
    __shared__ int    sgid[WMAX];
    __shared__ int    cnt[NBKT], st[NBKT + 1], fil[NBKT];
    __shared__ int    rr0[9], roff[10], rcnt_s;

    const int tid = threadIdx.x;
    const int i = blockIdx.x * 256 + tid;

    // ---- Phase A: histogram + rank ----
    if (i < N) {
        int c = (cell_coord(means[3*i+2]) * G + cell_coord(means[3*i+1])) * G
                + cell_coord(means[3*i+0]);
        g_gcell[i] = c;
        g_grank[i] = atomicAdd(&g_cnt[c], 1);
    }
    if (i < M) {
        int c = (cell_coord(coords[3*i+2]) * G + cell_coord(coords[3*i+1])) * G
                + cell_coord(coords[3*i+0]);
        g_qcell[i] = c;
        g_qrank[i] = atomicAdd(&g_qcnt[c], 1);
    }
    grid_bar(0);

    // ---- Phase B: scans (block 0) ----
    if (blockIdx.x == 0) {
        scan512_zero(g_cnt, g_start);
        scan512_zero(g_qcnt, g_qstart);
    }
    grid_bar(1);

    // ---- Phase C: scatter ----
    if (i < N) {
        int pos = g_start[g_gcell[i]] + g_grank[i];
        g_sorted[pos] = make_float4(means[3*i], means[3*i+1], means[3*i+2],
                                    __int_as_float(i));
        g_icov_s[pos] = make_float4(expf(-logc[3*i]), expf(-logc[3*i+1]),
                                    expf(-logc[3*i+2]), 0.f);
    }
    if (i < M) {
        int pos = g_qstart[g_qcell[i]] + g_qrank[i];
        g_qorder[pos] = i;
    }
    grid_bar(2);

    // ---- Phase D: window build, cell = blockIdx.x ----
    const int cell = blockIdx.x;
    const int cx = cell & 7, cy = (cell >> 3) & 7, cz = cell >> 6;
    const float ccx = (cx + 0.5f) * 0.125f;
    const float ccy = (cy + 0.5f) * 0.125f;
    const float ccz = (cz + 0.5f) * 0.125f;

    if (tid < NBKT) { cnt[tid] = 0; fil[tid] = 0; }
    const int x0 = max(cx - 1, 0), x1e = min(cx + 1, G - 1) + 1;
    if (tid == 0) {
        int rc = 0, n0 = 0;
        for (int z = max(cz - 1, 0); z <= min(cz + 1, G - 1); ++z) {
            for (int y = max(cy - 1, 0); y <= min(cy + 1, G - 1); ++y) {
                int base = (z * G + y) * G;
                int r0 = g_start[base + x0];
                int len = g_start[base + x1e] - r0;
                rr0[rc] = r0; roff[rc] = n0;
                n0 += len; rc++;
            }
        }
        roff[rc] = n0;
        rcnt_s = rc;
    }
    __syncthreads();

    const int rcnt = rcnt_s;
    const int n = roff[rcnt];
    const bool ovf = (n > WMAX);

    if (!ovf) {
        for (int ii = tid; ii < n; ii += 256) {
            int k = 0;
#pragma unroll
            for (int kk = 1; kk < 9; kk++)
                if (kk < rcnt && ii >= roff[kk]) k = kk;
            int src = rr0[k] + (ii - roff[k]);
            float4 g = g_sorted[src];
            float dx = g.x - ccx, dy = g.y - ccy, dz = g.z - ccz;
            float cd = fmaf(dx, dx, fmaf(dy, dy, dz * dz));
            spos4[ii] = g;
            skey[ii] = cd;
            sgid[ii] = src;
            atomicAdd(&cnt[min(NBKT - 1, (int)(cd * INVBW))], 1);
        }
    }
    __syncthreads();

    if (tid < 32) {
        int v = cnt[tid];
        for (int o = 1; o < 32; o <<= 1) {
            int u = __shfl_up_sync(0xffffffffu, v, o);
            if (tid >= o) v += u;
        }
        st[tid + 1] = v;
        if (tid == 0) st[0] = 0;
    }
    __syncthreads();

    int nsw = min(n, CAPW);
    if (ovf) nsw = 0;
    const int nswp = min(CAPW, (nsw + 31) & ~31);
    if (tid == 0) {
        float marg = 1e30f;
        if (ovf) marg = -1.f;
        else if (n > CAPW) {
            int t = 0;
            while (t < NBKT && st[t + 1] <= CAPW) t++;
            marg = (float)t * BWIDTH;
        }
        g_wmargin[cell] = marg;
        g_nsw[cell] = nsw;
        g_nswp[cell] = nswp;
    }
    __syncthreads();

    if (!ovf) {
        for (int ii = tid; ii < n; ii += 256) {
            float cd = skey[ii];
            int b = min(NBKT - 1, (int)(cd * INVBW));
            int pos = st[b] + atomicAdd(&fil[b], 1);
            if (pos < CAPW) {
                float4 gp = spos4[ii];
                float m2 = fmaf(gp.x, gp.x, fmaf(gp.y, gp.y, gp.z * gp.z)) + 3.f;
                g_winpos[cell * CAPW + pos] = make_float4(gp.x, gp.y, gp.z, m2);
                float4 ic = g_icov_s[sgid[ii]];
                g_winic[cell * CAPW + pos] = make_float4(ic.x, ic.y, ic.z, gp.w);
                g_wincd[cell * CAPW + pos] = cd;
            }
        }
        for (int ii = nsw + tid; ii < nswp; ii += 256) {
            g_winpos[cell * CAPW + ii] = make_float4(64.f, 64.f, 64.f,
                                                     3.f * 64.f * 64.f + 3.f);
            g_winic[cell * CAPW + ii] = make_float4(0.f, 0.f, 0.f,
                                                    __int_as_float(0));
            g_wincd[cell * CAPW + ii] = 1e30f;
        }
    }

    // ---- reset barriers for next graph replay ----
    __syncthreads();
    if (tid == 0) {
        __threadfence();
        int prev = atomicAdd(&g_bar[3], 1);
        if (prev == NC - 1) {
            g_bar[0] = 0; g_bar[1] = 0; g_bar[2] = 0; g_bar[3] = 0;
            __threadfence();
        }
    }
}

// Exact per-query fallback (rare).
__device__ __noinline__ void fallback_query(int q, float qx, float qy, float qz,
                                            int cx, int cy, int cz,
                                            const float4* __restrict__ feats4,
                                            float* __restrict__ out) {
    const float h = 1.0f / (float)G;
    float bd[KNN];
#pragma unroll
    for (int t = 0; t < KNN; t++) bd[t] = FLT_MAX;

    int rfin = 1;
    for (int r = 1; r <= G; ++r) {
        rfin = r;
        for (int dz = -r; dz <= r; ++dz) {
            int z = cz + dz; if ((unsigned)z >= G) continue;
            for (int dy = -r; dy <= r; ++dy) {
                int y = cy + dy; if ((unsigned)y >= G) continue;
                bool edge = (dz == -r) | (dz == r) | (dy == -r) | (dy == r);
                int step = (r > 1 && !edge) ? 2 * r : 1;
                for (int dx = -r; dx <= r; dx += step) {
                    int x = cx + dx; if ((unsigned)x >= G) continue;
                    int cid = (z * G + y) * G + x;
                    int c0 = g_start[cid], c1 = g_start[cid + 1];
                    for (int c = c0; c < c1; ++c) {
                        float4 g = g_sorted[c];
                        float ddx = qx - g.x, ddy = qy - g.y, ddz = qz - g.z;
                        float d2 = fmaf(ddx, ddx, fmaf(ddy, ddy, ddz * ddz));
                        if (d2 < bd[0]) {
                            bd[0] = d2;
#pragma unroll
                            for (int t = 0; t < KNN - 1; t++) {
                                float a = fmaxf(bd[t], bd[t+1]);
                                float b = fminf(bd[t], bd[t+1]);
                                bd[t] = a; bd[t+1] = b;
                            }
                        }
                    }
                }
            }
        }
        float m = 1e30f;
        if (cx - r > 0)     m = fminf(m, qx - (float)(cx - r) * h);
        if (cx + r < G - 1) m = fminf(m, (float)(cx + r + 1) * h - qx);
        if (cy - r > 0)     m = fminf(m, qy - (float)(cy - r) * h);
        if (cy + r < G - 1) m = fminf(m, (float)(cy + r + 1) * h - qy);
        if (cz - r > 0)     m = fminf(m, qz - (float)(cz - r) * h);
        if (cz + r < G - 1) m = fminf(m, (float)(cz + r + 1) * h - qz);
        if (bd[0] <= m * m) break;
    }
    const float T = bd[0];

    int myp[KNN];
#pragma unroll
    for (int t = 0; t < KNN; t++) myp[t] = 0;
    int cnt = 0;
    {
        const int r = rfin;
        for (int dz = -r; dz <= r; ++dz) {
            int z = cz + dz; if ((unsigned)z >= G) continue;
            for (int dy = -r; dy <= r; ++dy) {
                int y = cy + dy; if ((unsigned)y >= G) continue;
                for (int dx = -r; dx <= r; ++dx) {
                    int x = cx + dx; if ((unsigned)x >= G) continue;
                    int cid = (z * G + y) * G + x;
                    int c0 = g_start[cid], c1 = g_start[cid + 1];
                    for (int c = c0; c < c1; ++c) {
                        float4 g = g_sorted[c];
                        float ddx = qx - g.x, ddy = qy - g.y, ddz = qz - g.z;
                        float d2 = fmaf(ddx, ddx, fmaf(ddy, ddy, ddz * ddz));
                        if (d2 <= T && cnt < KNN) { myp[cnt] = c; cnt++; }
                    }
                }
            }
        }
    }

    float acc[NF];
#pragma unroll
    for (int f = 0; f < NF; f++) acc[f] = 0.f;
    float wsum = 0.f;
#pragma unroll
    for (int t = 0; t < KNN; t++) {
        int p = myp[t];
        float4 g = g_sorted[p];
        float4 ic = g_icov_s[p];
        int id = __float_as_int(g.w);
        float ddx = qx - g.x, ddy = qy - g.y, ddz = qz - g.z;
        float e = fmaf(ddx*ddx, ic.x, fmaf(ddy*ddy, ic.y, ddz*ddz*ic.z));
        float wgt = __expf(-0.5f * e);
        wsum += wgt;
        const float4* fp = feats4 + (size_t)id * (NF/4);
#pragma unroll
        for (int cc = 0; cc < NF/4; cc++) {
            float4 fv = fp[cc];
            acc[4*cc+0] = fmaf(wgt, fv.x, acc[4*cc+0]);
            acc[4*cc+1] = fmaf(wgt, fv.y, acc[4*cc+1]);
            acc[4*cc+2] = fmaf(wgt, fv.z, acc[4*cc+2]);
            acc[4*cc+3] = fmaf(wgt, fv.w, acc[4*cc+3]);
        }
    }
    float inv = 1.f / (wsum + 1e-8f);
    float4* o4 = (float4*)(out + (size_t)q * NF);
#pragma unroll
    for (int cc = 0; cc < NF/4; cc++)
        o4[cc] = make_float4(acc[4*cc+0]*inv, acc[4*cc+1]*inv,
                             acc[4*cc+2]*inv, acc[4*cc+3]*inv);
}

#define CSWAP(A, i, j) { unsigned a_ = umax(A[i], A[j]); unsigned b_ = umin(A[i], A[j]); A[i] = a_; A[j] = b_; }
// Descending bitonic merge of a 16-element bitonic sequence.
__device__ __forceinline__ void bmerge16(unsigned a[16]) {
#pragma unroll
    for (int i = 0; i < 8; i++) CSWAP(a, i, i + 8);
#pragma unroll
    for (int h = 0; h < 16; h += 8)
#pragma unroll
        for (int i = 0; i < 4; i++) CSWAP(a, h + i, h + i + 4);
#pragma unroll
    for (int h = 0; h < 16; h += 4)
#pragma unroll
        for (int i = 0; i < 2; i++) CSWAP(a, h + i, h + i + 2);
#pragma unroll
    for (int i = 0; i < 16; i += 2) CSWAP(a, i, i + 1);
}

// Main: 8 lanes/query, 4 queries/warp, 3-stage exact merge, distributed epilogue.
__global__ __launch_bounds__(256, 4)
void splash_q(const float* __restrict__ coords,
              const float4* __restrict__ feats4,
              float* __restrict__ out, int M) {
    const int gw = (blockIdx.x * 256 + threadIdx.x) >> 5;
    const int lane = threadIdx.x & 31;
    const int L = lane & 7;
    const int qslot = gw * 4 + (lane >> 3);
    const bool has = qslot < M;

    const int q = g_qorder[has ? qslot : 0];
    const float qx = coords[3*q+0], qy = coords[3*q+1], qz = coords[3*q+2];
    const int cx = cell_coord(qx), cy = cell_coord(qy), cz = cell_coord(qz);
    const int cell = (cz * G + cy) * G + cx;
    const int cb = cell * CAPW;
    const int nSW = g_nsw[cell];
    const int nSWP = g_nswp[cell];
    const float wmarg = g_wmargin[cell];

    const float qq = fmaf(qx, qx, fmaf(qy, qy, qz * qz));
    const float n2x = -2.f * qx, n2y = -2.f * qy, n2z = -2.f * qz;
    const float ccx = (cx + 0.5f) * 0.125f;
    const float ccy = (cy + 0.5f) * 0.125f;
    const float ccz = (cz + 0.5f) * 0.125f;
    float rdx = qx - ccx, rdy = qy - ccy, rdz = qz - ccz;
    const float rq = sqrtf(fmaf(rdx, rdx, fmaf(rdy, rdy, rdz * rdz)));

    const bool mainable = has && nSW >= 32 && wmarg >= 0.f;

    unsigned key[KD];
#pragma unroll
    for (int t = 0; t < KD; t++) key[t] = 0xFFFFFFFFu;

    bool done = !mainable;
    for (int base = 0; !__all_sync(0xffffffffu, done); base += 32) {
        if (!done) {
            float ncd = __ldg(&g_wincd[cb + base + 32]);
            float tv[4];
#pragma unroll
            for (int k = 0; k < 4; k++) {
                float4 g = __ldg(&g_winpos[cb + base + L + 8 * k]);
                tv[k] = fmaf(g.x, n2x, fmaf(g.y, n2y, fmaf(g.z, n2z, g.w)));
            }
#pragma unroll
            for (int k = 0; k < 4; k++) {
                int j = base + L + 8 * k;
                unsigned kn = (__float_as_uint(tv[k]) & ~IDXMASK) | (unsigned)j;
                if (kn < key[0]) {
                    key[0] = kn;
#pragma unroll
                    for (int s = 0; s < KD - 1; s++) {
                        unsigned a = umax(key[s], key[s+1]);
                        unsigned b = umin(key[s], key[s+1]);
                        key[s] = a; key[s+1] = b;
                    }
                }
            }
            if (base + 32 >= nSWP) done = true;
            else {
                float d8sq = __uint_as_float(key[0] & ~IDXMASK) - 3.f + qq;
                if (d8sq >= 0.f) {
                    float dn = sqrtf(d8sq) + rq;
                    if (ncd - BWIDTH > dn * dn) done = true;
                }
            }
        }
    }

    // Stage 1 (xor 1): union of two sorted-8 lists -> bitonic 16 -> sort desc.
    unsigned e[16];
#pragma unroll
    for (int t = 0; t < 8; t++) e[t] = key[t];
#pragma unroll
    for (int t = 0; t < 8; t++)
        e[8 + t] = __shfl_xor_sync(0xffffffffu, key[7 - t], 1);
    bmerge16(e);
    // Stage 2 (xor 2): min-trick top-16 of 32 -> sort desc.
    {
        unsigned p[16];
#pragma unroll
        for (int t = 0; t < 16; t++)
            p[t] = __shfl_xor_sync(0xffffffffu, e[15 - t], 2);
#pragma unroll
        for (int t = 0; t < 16; t++) e[t] = umin(e[t], p[t]);
        bmerge16(e);
    }
    // Stage 3 (xor 4): min-trick top-16 of 32 -> sort desc. All 8 lanes identical.
    {
        unsigned p[16];
#pragma unroll
        for (int t = 0; t < 16; t++)
            p[t] = __shfl_xor_sync(0xffffffffu, e[15 - t], 4);
#pragma unroll
        for (int t = 0; t < 16; t++) e[t] = umin(e[t], p[t]);
        bmerge16(e);
    }
    const unsigned mx = e[0];   // global 16th smallest

    // Safety: every lane's worst-kept must be >= global 16th (validates both
    // evictions and early-exit skips exactly).
    bool lane_ok = (key[0] >= mx);
    unsigned bal = __ballot_sync(0xffffffffu, lane_ok);
    bool oct_ok = (((bal >> (lane & ~7)) & 0xFFu) == 0xFFu);

    float d16sq = __uint_as_float(mx & ~IDXMASK) - 3.f + qq;
    const float h = 0.125f;
    float m = 1e30f;
    if (cx - 1 > 0)     m = fminf(m, qx - (float)(cx - 1) * h);
    if (cx + 1 < G - 1) m = fminf(m, (float)(cx + 2) * h - qx);
    if (cy - 1 > 0)     m = fminf(m, qy - (float)(cy - 1) * h);
    if (cy + 1 < G - 1) m = fminf(m, (float)(cy + 2) * h - qy);
    if (cz - 1 > 0)     m = fminf(m, qz - (float)(cz - 1) * h);
    if (cz + 1 < G - 1) m = fminf(m, (float)(cz + 2) * h - qz);

    float d16c = sqrtf(fmaxf(d16sq, 0.f));
    bool ok = mainable && oct_ok && (d16sq <= m * m)
              && ((d16c + rq) * (d16c + rq) <= wmarg);

    if (has && !ok && L == 0)
        fallback_query(q, qx, qy, qz, cx, cy, cz, feats4, out);

    if (has && ok) {
        unsigned am = __activemask();   // whole octets active together

        // Lane's 2 canonical neighbors: e[2L], e[2L+1] (predicated extract).
        unsigned kv0 = 0, kv1 = 0;
#pragma unroll
        for (int t = 0; t < 16; t += 2) {
            bool sel = ((t >> 1) == L);
            kv0 = sel ? e[t]     : kv0;
            kv1 = sel ? e[t + 1] : kv1;
        }
        float wgt[2];
        int   idv[2];
#pragma unroll
        for (int kk = 0; kk < 2; kk++) {
            int p = (int)((kk ? kv1 : kv0) & IDXMASK);
            float4 g = __ldg(&g_winpos[cb + p]);
            float4 ic = __ldg(&g_winic[cb + p]);
            idv[kk] = __float_as_int(ic.w);
            float ddx = qx - g.x, ddy = qy - g.y, ddz = qz - g.z;
            float e2 = fmaf(ddx*ddx, ic.x, fmaf(ddy*ddy, ic.y, ddz*ddz*ic.z));
            wgt[kk] = __expf(-0.5f * e2);
        }

        const int qb = lane & ~7;
        float a0 = 0.f, a1 = 0.f, a2 = 0.f, a3 = 0.f;
        float wsum = 0.f;
#pragma unroll
        for (int t = 0; t < KNN; t++) {
            float w  = __shfl_sync(am, wgt[t & 1], qb + (t >> 1));
            int  id  = __shfl_sync(am, idv[t & 1], qb + (t >> 1));
            wsum += w;
            float4 fv = __ldg(feats4 + (size_t)id * (NF/4) + L);
            a0 = fmaf(w, fv.x, a0);
            a1 = fmaf(w, fv.y, a1);
            a2 = fmaf(w, fv.z, a2);
            a3 = fmaf(w, fv.w, a3);
        }
        float inv = 1.f / (wsum + 1e-8f);
        float4* o4 = (float4*)(out + (size_t)q * NF);
        o4[L] = make_float4(a0 * inv, a1 * inv, a2 * inv, a3 * inv);
    }
}

extern "C" void kernel_launch(void* const* d_in, const int* in_sizes, int n_in,
                              void* d_out, int out_size) {
    const float* coords = (const float*)d_in[0];
    const float* means  = (const float*)d_in[1];
    const float* logc   = (const float*)d_in[2];
    const float* feats  = (const float*)d_in[3];
    float* out = (float*)d_out;

    int M = in_sizes[0] / 3;
    int N = in_sizes[1] / 3;

    k_prep<<<NC, 256>>>(coords, means, logc, N, M);
    int qblocks = (M * 8 + 255) / 256;
    splash_q<<<qblocks, 256>>>(coords, (const float4*)feats, out, M);
}

// round 13
// speedup vs baseline: 1.6584x; 1.6584x over previous
#include <cuda_runtime.h>
#include <math.h>
#include <float.h>

#define G 8
#define NC (G*G*G)
#define MAXN 10016
#define MAXM 32768
#define KNN 16
#define NF 32
#define CAPW 512
#define WMAX 1024
#define NBKT 32
#define KD 12
#define IDXMASK 0x1FFu
#define CDMAX 0.1055f
#define BWIDTH (CDMAX / (float)NBKT)
#define INVBW ((float)NBKT / CDMAX)

// ---- device scratch (allocation-free) ----
__device__ float4 g_sorted[MAXN];
__device__ float4 g_icov_s[MAXN];
__device__ int g_cnt[NC], g_start[NC + 1];
__device__ int g_qcnt[NC], g_qstart[NC + 1];
__device__ int g_gcell[MAXN], g_grank[MAXN];
__device__ int g_qcell[MAXM], g_qrank[MAXM];
__device__ int g_qorder[MAXM];
__device__ int g_done;

__device__ __forceinline__ int cell_coord(float v) {
    int c = (int)(v * (float)G);
    return min(G - 1, max(0, c));
}

// 512-entry exclusive scan with 256 threads (2 entries/thread); zeroes src.
__device__ void scan512_zero(int* src, int* dst) {
    __shared__ int ws[8];
    int t = threadIdx.x, lane = t & 31, w = t >> 5;
    int c0 = src[2 * t], c1 = src[2 * t + 1];
    src[2 * t] = 0; src[2 * t + 1] = 0;
    int s = c0 + c1;
    int v = s;
    for (int o = 1; o < 32; o <<= 1) {
        int u = __shfl_up_sync(0xffffffffu, v, o);
        if (lane >= o) v += u;
    }
    if (lane == 31) ws[w] = v;
    __syncthreads();
    if (t < 32) {
        int p = (t < 8) ? ws[t] : 0;
        for (int o = 1; o < 8; o <<= 1) {
            int u = __shfl_up_sync(0xffffffffu, p, o);
            if (t >= o) p += u;
        }
        if (t < 8) ws[t] = p;
    }
    __syncthreads();
    int incl = v + (w ? ws[w - 1] : 0);
    int excl = incl - s;
    dst[2 * t + 1] = excl + c0;
    dst[2 * t + 2] = incl;
    if (t == 0) dst[0] = 0;
    __syncthreads();
}

// Histogram + (in the last finishing block) both exclusive scans.
__global__ void k_hist(const float* __restrict__ means, int N,
                       const float* __restrict__ coords, int M) {
    int i = blockIdx.x * blockDim.x + threadIdx.x;
    if (i < N) {
        int c = (cell_coord(means[3*i+2]) * G + cell_coord(means[3*i+1])) * G
                + cell_coord(means[3*i+0]);
        g_gcell[i] = c;
        g_grank[i] = atomicAdd(&g_cnt[c], 1);
    }
    if (i < M) {
        int c = (cell_coord(coords[3*i+2]) * G + cell_coord(coords[3*i+1])) * G
                + cell_coord(coords[3*i+0]);
        g_qcell[i] = c;
        g_qrank[i] = atomicAdd(&g_qcnt[c], 1);
    }
    __threadfence();
    __shared__ int is_last;
    if (threadIdx.x == 0) {
        int prev = atomicAdd(&g_done, 1);
        is_last = (prev == (int)gridDim.x - 1);
    }
    __syncthreads();
    if (!is_last) return;
    if (threadIdx.x == 0) g_done = 0;
    scan512_zero(g_cnt, g_start);
    scan512_zero(g_qcnt, g_qstart);
}

__global__ void k_scatter(const float* __restrict__ means,
                          const float* __restrict__ logc, int N, int M) {
    int i = blockIdx.x * blockDim.x + threadIdx.x;
    if (i < N) {
        int pos = g_start[g_gcell[i]] + g_grank[i];
        g_sorted[pos] = make_float4(means[3*i], means[3*i+1], means[3*i+2],
                                    __int_as_float(i));
        g_icov_s[pos] = make_float4(expf(-logc[3*i]), expf(-logc[3*i+1]),
                                    expf(-logc[3*i+2]), 0.f);
    }
    if (i < M) {
        int pos = g_qstart[g_qcell[i]] + g_qrank[i];
        g_qorder[pos] = i;
    }
}

// Exact per-query fallback (rare): gmem ring expansion + threshold rescan.
__device__ __noinline__ void fallback_query(int q, float qx, float qy, float qz,
                                            int cx, int cy, int cz,
                                            const float4* __restrict__ feats4,
                                            float* __restrict__ out) {
    const float h = 1.0f / (float)G;
    float bd[KNN];
#pragma unroll
    for (int t = 0; t < KNN; t++) bd[t] = FLT_MAX;

    int rfin = 1;
    for (int r = 1; r <= G; ++r) {
        rfin = r;
        for (int dz = -r; dz <= r; ++dz) {
            int z = cz + dz; if ((unsigned)z >= G) continue;
            for (int dy = -r; dy <= r; ++dy) {
                int y = cy + dy; if ((unsigned)y >= G) continue;
                bool edge = (dz == -r) | (dz == r) | (dy == -r) | (dy == r);
                int step = (r > 1 && !edge) ? 2 * r : 1;
                for (int dx = -r; dx <= r; dx += step) {
                    int x = cx + dx; if ((unsigned)x >= G) continue;
                    int cid = (z * G + y) * G + x;
                    int c0 = g_start[cid], c1 = g_start[cid + 1];
                    for (int c = c0; c < c1; ++c) {
                        float4 g = g_sorted[c];
                        float ddx = qx - g.x, ddy = qy - g.y, ddz = qz - g.z;
                        float d2 = fmaf(ddx, ddx, fmaf(ddy, ddy, ddz * ddz));
                        if (d2 < bd[0]) {
                            bd[0] = d2;
#pragma unroll
                            for (int t = 0; t < KNN - 1; t++) {
                                float a = fmaxf(bd[t], bd[t+1]);
                                float b = fminf(bd[t], bd[t+1]);
                                bd[t] = a; bd[t+1] = b;
                            }
                        }
                    }
                }
            }
        }
        float m = 1e30f;
        if (cx - r > 0)     m = fminf(m, qx - (float)(cx - r) * h);
        if (cx + r < G - 1) m = fminf(m, (float)(cx + r + 1) * h - qx);
        if (cy - r > 0)     m = fminf(m, qy - (float)(cy - r) * h);
        if (cy + r < G - 1) m = fminf(m, (float)(cy + r + 1) * h - qy);
        if (cz - r > 0)     m = fminf(m, qz - (float)(cz - r) * h);
        if (cz + r < G - 1) m = fminf(m, (float)(cz + r + 1) * h - qz);
        if (bd[0] <= m * m) break;
    }
    const float T = bd[0];

    int myp[KNN];
#pragma unroll
    for (int t = 0; t < KNN; t++) myp[t] = 0;
    int cnt = 0;
    {
        const int r = rfin;
        for (int dz = -r; dz <= r; ++dz) {
            int z = cz + dz; if ((unsigned)z >= G) continue;
            for (int dy = -r; dy <= r; ++dy) {
                int y = cy + dy; if ((unsigned)y >= G) continue;
                for (int dx = -r; dx <= r; ++dx) {
                    int x = cx + dx; if ((unsigned)x >= G) continue;
                    int cid = (z * G + y) * G + x;
                    int c0 = g_start[cid], c1 = g_start[cid + 1];
                    for (int c = c0; c < c1; ++c) {
                        float4 g = g_sorted[c];
                        float ddx = qx - g.x, ddy = qy - g.y, ddz = qz - g.z;
                        float d2 = fmaf(ddx, ddx, fmaf(ddy, ddy, ddz * ddz));
                        if (d2 <= T && cnt < KNN) { myp[cnt] = c; cnt++; }
                    }
                }
            }
        }
    }

    float acc[NF];
#pragma unroll
    for (int f = 0; f < NF; f++) acc[f] = 0.f;
    float wsum = 0.f;
#pragma unroll
    for (int t = 0; t < KNN; t++) {
        int p = myp[t];
        float4 g = g_sorted[p];
        float4 ic = g_icov_s[p];
        int id = __float_as_int(g.w);
        float ddx = qx - g.x, ddy = qy - g.y, ddz = qz - g.z;
        float e = fmaf(ddx*ddx, ic.x, fmaf(ddy*ddy, ic.y, ddz*ddz*ic.z));
        float wgt = __expf(-0.5f * e);
        wsum += wgt;
        const float4* fp = feats4 + (size_t)id * (NF/4);
#pragma unroll
        for (int cc = 0; cc < NF/4; cc++) {
            float4 fv = fp[cc];
            acc[4*cc+0] = fmaf(wgt, fv.x, acc[4*cc+0]);
            acc[4*cc+1] = fmaf(wgt, fv.y, acc[4*cc+1]);
            acc[4*cc+2] = fmaf(wgt, fv.z, acc[4*cc+2]);
            acc[4*cc+3] = fmaf(wgt, fv.w, acc[4*cc+3]);
        }
    }
    float inv = 1.f / (wsum + 1e-8f);
    float4* o4 = (float4*)(out + (size_t)q * NF);
#pragma unroll
    for (int cc = 0; cc < NF/4; cc++)
        o4[cc] = make_float4(acc[4*cc+0]*inv, acc[4*cc+1]*inv,
                             acc[4*cc+2]*inv, acc[4*cc+3]*inv);
}

// Main: one block per cell. Radially-sorted window built in SMEM, then
// 4 lanes/query scan (LDS broadcast), exact quad merge, per-lane epilogue.
__global__ __launch_bounds__(256, 3)
void splash_cell(const float* __restrict__ coords,
                 const float4* __restrict__ feats4,
                 float* __restrict__ out) {
    __shared__ float4 sstage[WMAX];          // staged positions (build)
    __shared__ float  skey[WMAX];
    __shared__ int    sgid[WMAX];
    __shared__ float4 spos[CAPW];            // window positions (x,y,z,|m|^2+3)
    __shared__ float4 sicv[CAPW];            // window icov (.w = orig id bits)
    __shared__ float  scd[CAPW + 32];        // center-dist^2 (+slack)
    __shared__ int    cnt[NBKT], st[NBKT + 1], fil[NBKT];
    __shared__ int    rr0[9], roff[10], rcnt_s;
    __shared__ int    nsw_s, nswp_s;
    __shared__ float  wmarg_s;

    const int cell = blockIdx.x;
    const int q0 = g_qstart[cell], q1 = g_qstart[cell + 1];
    if (q0 == q1) return;
    const int tid = threadIdx.x;

    // ---- window build (bucket counting-sort by center distance) ----
    const int cx = cell & 7, cy = (cell >> 3) & 7, cz = cell >> 6;
    const float ccx = (cx + 0.5f) * 0.125f;
    const float ccy = (cy + 0.5f) * 0.125f;
    const float ccz = (cz + 0.5f) * 0.125f;

    if (tid < NBKT) { cnt[tid] = 0; fil[tid] = 0; }
    const int x0 = max(cx - 1, 0), x1e = min(cx + 1, G - 1) + 1;
    if (tid == 0) {
        int rc = 0, n0 = 0;
        for (int z = max(cz - 1, 0); z <= min(cz + 1, G - 1); ++z) {
            for (int y = max(cy - 1, 0); y <= min(cy + 1, G - 1); ++y) {
                int base = (z * G + y) * G;
                int r0 = g_start[base + x0];
                int len = g_start[base + x1e] - r0;
                rr0[rc] = r0; roff[rc] = n0;
                n0 += len; rc++;
            }
        }
        roff[rc] = n0;
        rcnt_s = rc;
    }
    __syncthreads();

    const int rcnt = rcnt_s;
    const int n = roff[rcnt];
    const bool ovf = (n > WMAX);

    if (!ovf) {
        for (int i = tid; i < n; i += 256) {
            int k = 0;
#pragma unroll
            for (int kk = 1; kk < 9; kk++)
                if (kk < rcnt && i >= roff[kk]) k = kk;
            int src = rr0[k] + (i - roff[k]);
            float4 g = g_sorted[src];
            float dx = g.x - ccx, dy = g.y - ccy, dz = g.z - ccz;
            float cd = fmaf(dx, dx, fmaf(dy, dy, dz * dz));
            sstage[i] = g;
            skey[i] = cd;
            sgid[i] = src;
            atomicAdd(&cnt[min(NBKT - 1, (int)(cd * INVBW))], 1);
        }
    }
    __syncthreads();

    if (tid < 32) {
        int v = cnt[tid];
        for (int o = 1; o < 32; o <<= 1) {
            int u = __shfl_up_sync(0xffffffffu, v, o);
            if (tid >= o) v += u;
        }
        st[tid + 1] = v;
        if (tid == 0) st[0] = 0;
    }
    __syncthreads();

    if (tid == 0) {
        int nsw = ovf ? 0 : min(n, CAPW);
        float marg = 1e30f;
        if (ovf) marg = -1.f;
        else if (n > CAPW) {
            int t = 0;
            while (t < NBKT && st[t + 1] <= CAPW) t++;
            marg = (float)t * BWIDTH;
        }
        nsw_s = nsw;
        nswp_s = min(CAPW, (nsw + 31) & ~31);
        wmarg_s = marg;
    }
    __syncthreads();

    const int nSW = nsw_s, nSWP = nswp_s;
    const float wmarg = wmarg_s;

    if (!ovf) {
        for (int i = tid; i < n; i += 256) {
            float cd = skey[i];
            int b = min(NBKT - 1, (int)(cd * INVBW));
            int pos = st[b] + atomicAdd(&fil[b], 1);
            if (pos < CAPW) {
                float4 gp = sstage[i];
                float m2 = fmaf(gp.x, gp.x, fmaf(gp.y, gp.y, gp.z * gp.z)) + 3.f;
                spos[pos] = make_float4(gp.x, gp.y, gp.z, m2);
                float4 ic = g_icov_s[sgid[i]];
                sicv[pos] = make_float4(ic.x, ic.y, ic.z, gp.w);
                scd[pos] = cd;
            }
        }
        for (int i = nSW + tid; i < nSWP; i += 256) {
            spos[i] = make_float4(64.f, 64.f, 64.f, 3.f * 64.f * 64.f + 3.f);
            sicv[i] = make_float4(0.f, 0.f, 0.f, __int_as_float(0));
            scd[i] = 1e30f;
        }
    }
    __syncthreads();

    // ---- query processing: 4 lanes/query, quads strided over the cell ----
    const int lane = tid & 31;
    const int L = lane & 3;
    const int quad = tid >> 2;          // 0..63
    const float h = 0.125f;
    const int nq = q1 - q0;
    const int nrounds = (nq + 63) >> 6;

    for (int rr = 0; rr < nrounds; rr++) {
        const int qi = q0 + quad + (rr << 6);
        const bool has = qi < q1;
        const int q = g_qorder[has ? qi : q0];
        const float qx = coords[3*q+0], qy = coords[3*q+1], qz = coords[3*q+2];
        const float qq = fmaf(qx, qx, fmaf(qy, qy, qz * qz));
        const float n2x = -2.f * qx, n2y = -2.f * qy, n2z = -2.f * qz;
        float rdx = qx - ccx, rdy = qy - ccy, rdz = qz - ccz;
        const float rq = sqrtf(fmaf(rdx, rdx, fmaf(rdy, rdy, rdz * rdz)));

        const bool mainable = has && nSW >= 32 && wmarg >= 0.f;

        unsigned key[KD];
#pragma unroll
        for (int t = 0; t < KD; t++) key[t] = 0xFFFFFFFFu;

        bool done = !mainable;
        for (int base = 0; !__all_sync(0xffffffffu, done); base += 32) {
            if (!done) {
                float ncd = scd[base + 32];
                float tv[8];
#pragma unroll
                for (int k = 0; k < 8; k++) {
                    float4 g = spos[base + L + 4 * k];
                    tv[k] = fmaf(g.x, n2x, fmaf(g.y, n2y, fmaf(g.z, n2z, g.w)));
                }
#pragma unroll
                for (int k = 0; k < 8; k++) {
                    int j = base + L + 4 * k;
                    unsigned kn = (__float_as_uint(tv[k]) & ~IDXMASK) | (unsigned)j;
                    if (kn < key[0]) {
                        key[0] = kn;
#pragma unroll
                        for (int s = 0; s < KD - 1; s++) {
                            unsigned a = umax(key[s], key[s+1]);
                            unsigned b = umin(key[s], key[s+1]);
                            key[s] = a; key[s+1] = b;
                        }
                    }
                }
                if (base + 32 >= nSWP) done = true;
                else {
                    float d16sq = __uint_as_float(key[0] & ~IDXMASK) - 3.f + qq;
                    if (d16sq >= 0.f) {
                        float dn = sqrtf(d16sq) + rq;
                        if (ncd - BWIDTH > dn * dn) done = true;
                    }
                }
            }
        }

        // Two-stage exact quad merge (pads inlined: slots 0..3 are +inf).
#define PK_(i) ((i) < 4 ? 0xFFFFFFFFu : key[(i) - 4])
        unsigned e[16];
#pragma unroll
        for (int t = 0; t < 16; t++) {
            unsigned pp = __shfl_xor_sync(0xffffffffu, PK_(15 - t), 1);
            e[t] = umin(PK_(t), pp);
        }
#undef PK_
#define CE_(i, j) { unsigned a_ = umax(e[i], e[j]); unsigned b_ = umin(e[i], e[j]); e[i] = a_; e[j] = b_; }
#pragma unroll
        for (int i = 0; i < 8; i++) CE_(i, i + 8);
#pragma unroll
        for (int hb = 0; hb < 16; hb += 8)
#pragma unroll
            for (int i = 0; i < 4; i++) CE_(hb + i, hb + i + 4);
#pragma unroll
        for (int hb = 0; hb < 16; hb += 4)
#pragma unroll
            for (int i = 0; i < 2; i++) CE_(hb + i, hb + i + 2);
#pragma unroll
        for (int i = 0; i < 16; i += 2) CE_(i, i + 1);
#undef CE_

        unsigned gk[16];
#pragma unroll
        for (int t = 0; t < 16; t++) {
            unsigned pp = __shfl_xor_sync(0xffffffffu, e[15 - t], 2);
            gk[t] = umin(e[t], pp);
        }
        unsigned mx = gk[0];
#pragma unroll
        for (int t = 1; t < 16; t++) mx = umax(mx, gk[t]);

        bool lane_ok = (key[0] >= mx);
        unsigned bal = __ballot_sync(0xffffffffu, lane_ok);
        bool quad_ok = (((bal >> (lane & ~3)) & 0xFu) == 0xFu);

        float d16sq = __uint_as_float(mx & ~IDXMASK) - 3.f + qq;
        float m = 1e30f;
        if (cx - 1 > 0)     m = fminf(m, qx - (float)(cx - 1) * h);
        if (cx + 1 < G - 1) m = fminf(m, (float)(cx + 2) * h - qx);
        if (cy - 1 > 0)     m = fminf(m, qy - (float)(cy - 1) * h);
        if (cy + 1 < G - 1) m = fminf(m, (float)(cy + 2) * h - qy);
        if (cz - 1 > 0)     m = fminf(m, qz - (float)(cz - 1) * h);
        if (cz + 1 < G - 1) m = fminf(m, (float)(cz + 2) * h - qz);

        float d16c = sqrtf(fmaxf(d16sq, 0.f));
        bool ok = mainable && quad_ok && (d16sq <= m * m)
                  && ((d16c + rq) * (d16c + rq) <= wmarg);

        if (has && !ok && L == 0)
            fallback_query(q, qx, qy, qz, cx, cy, cz, feats4, out);

        if (has && ok) {
            float acc[NF/4];
#pragma unroll
            for (int f = 0; f < NF/4; f++) acc[f] = 0.f;
            float wsum = 0.f;
#pragma unroll
            for (int t = 0; t < KNN; t++) {
                int p = (int)(gk[t] & IDXMASK);
                float4 g = spos[p];
                float4 ic = sicv[p];
                int id = __float_as_int(ic.w);
                float ddx = qx - g.x, ddy = qy - g.y, ddz = qz - g.z;
                float e2 = fmaf(ddx*ddx, ic.x, fmaf(ddy*ddy, ic.y, ddz*ddz*ic.z));
                float wgt = __expf(-0.5f * e2);
                wsum += wgt;
                const float4* fp = feats4 + (size_t)id * (NF/4) + L * 2;
                float4 f0 = __ldg(&fp[0]);
                float4 f1 = __ldg(&fp[1]);
                acc[0] = fmaf(wgt, f0.x, acc[0]);
                acc[1] = fmaf(wgt, f0.y, acc[1]);
                acc[2] = fmaf(wgt, f0.z, acc[2]);
                acc[3] = fmaf(wgt, f0.w, acc[3]);
                acc[4] = fmaf(wgt, f1.x, acc[4]);
                acc[5] = fmaf(wgt, f1.y, acc[5]);
                acc[6] = fmaf(wgt, f1.z, acc[6]);
                acc[7] = fmaf(wgt, f1.w, acc[7]);
            }
            float inv = 1.f / (wsum + 1e-8f);
            float4* o4 = (float4*)(out + (size_t)q * NF) + L * 2;
            o4[0] = make_float4(acc[0]*inv, acc[1]*inv, acc[2]*inv, acc[3]*inv);
            o4[1] = make_float4(acc[4]*inv, acc[5]*inv, acc[6]*inv, acc[7]*inv);
        }
    }
}

extern "C" void kernel_launch(void* const* d_in, const int* in_sizes, int n_in,
                              void* d_out, int out_size) {
    const float* coords = (const float*)d_in[0];
    const float* means  = (const float*)d_in[1];
    const float* logc   = (const float*)d_in[2];
    const float* feats  = (const float*)d_in[3];
    float* out = (float*)d_out;

    int M = in_sizes[0] / 3;
    int N = in_sizes[1] / 3;
    int mx = (M > N ? M : N);

    k_hist<<<(mx + 255) / 256, 256>>>(means, N, coords, M);
    k_scatter<<<(mx + 255) / 256, 256>>>(means, logc, N, M);
    splash_cell<<<NC, 256>>>(coords, (const float4*)feats, out);
}

// round 14
// speedup vs baseline: 1.6595x; 1.0007x over previous
#include <cuda_runtime.h>
#include <math.h>
#include <float.h>

#define G 8
#define NC (G*G*G)
#define MAXN 10016
#define MAXM 32768
#define KNN 16
#define NF 32
#define CAPW 512
#define WMAX 1024
#define NBKT 32
#define KD 12
#define IDXMASK 0x1FFu
#define CDMAX 0.1055f
#define BWIDTH (CDMAX / (float)NBKT)
#define INVBW ((float)NBKT / CDMAX)

// ---- device scratch (allocation-free) ----
__device__ float4 g_sorted[MAXN];
__device__ float4 g_icov_s[MAXN];
__device__ int g_cnt[NC], g_start[NC + 1];
__device__ int g_qcnt[NC], g_qstart[NC + 1];
__device__ int g_gcell[MAXN], g_grank[MAXN];
__device__ int g_qcell[MAXM], g_qrank[MAXM];
__device__ int g_qorder[MAXM];
__device__ int g_done;

__device__ __forceinline__ int cell_coord(float v) {
    int c = (int)(v * (float)G);
    return min(G - 1, max(0, c));
}

// 512-entry exclusive scan with 256 threads (2 entries/thread); zeroes src.
__device__ void scan512_zero(int* src, int* dst) {
    __shared__ int ws[8];
    int t = threadIdx.x, lane = t & 31, w = t >> 5;
    int c0 = src[2 * t], c1 = src[2 * t + 1];
    src[2 * t] = 0; src[2 * t + 1] = 0;
    int s = c0 + c1;
    int v = s;
    for (int o = 1; o < 32; o <<= 1) {
        int u = __shfl_up_sync(0xffffffffu, v, o);
        if (lane >= o) v += u;
    }
    if (lane == 31) ws[w] = v;
    __syncthreads();
    if (t < 32) {
        int p = (t < 8) ? ws[t] : 0;
        for (int o = 1; o < 8; o <<= 1) {
            int u = __shfl_up_sync(0xffffffffu, p, o);
            if (t >= o) p += u;
        }
        if (t < 8) ws[t] = p;
    }
    __syncthreads();
    int incl = v + (w ? ws[w - 1] : 0);
    int excl = incl - s;
    dst[2 * t + 1] = excl + c0;
    dst[2 * t + 2] = incl;
    if (t == 0) dst[0] = 0;
    __syncthreads();
}

// Histogram + (in the last finishing block) both exclusive scans.
// NO __threadfence: g_cnt/g_qcnt are only mutated via atomicAdd-with-return
// (globally complete at L2 before the thread proceeds), and the scanning
// block's L1 has never cached those lines (flushed at launch), so its loads
// observe the final L2 values. Plain stores (g_gcell etc.) are consumed only
// after the kernel boundary.
__global__ void k_hist(const float* __restrict__ means, int N,
                       const float* __restrict__ coords, int M) {
    int i = blockIdx.x * blockDim.x + threadIdx.x;
    if (i < N) {
        int c = (cell_coord(means[3*i+2]) * G + cell_coord(means[3*i+1])) * G
                + cell_coord(means[3*i+0]);
        g_gcell[i] = c;
        g_grank[i] = atomicAdd(&g_cnt[c], 1);
    }
    if (i < M) {
        int c = (cell_coord(coords[3*i+2]) * G + cell_coord(coords[3*i+1])) * G
                + cell_coord(coords[3*i+0]);
        g_qcell[i] = c;
        g_qrank[i] = atomicAdd(&g_qcnt[c], 1);
    }
    __syncthreads();
    __shared__ int is_last;
    if (threadIdx.x == 0) {
        int prev = atomicAdd(&g_done, 1);
        is_last = (prev == (int)gridDim.x - 1);
    }
    __syncthreads();
    if (!is_last) return;
    if (threadIdx.x == 0) g_done = 0;
    scan512_zero(g_cnt, g_start);
    scan512_zero(g_qcnt, g_qstart);
}

__global__ void k_scatter(const float* __restrict__ means,
                          const float* __restrict__ logc, int N, int M) {
    int i = blockIdx.x * blockDim.x + threadIdx.x;
    if (i < N) {
        int pos = g_start[g_gcell[i]] + g_grank[i];
        g_sorted[pos] = make_float4(means[3*i], means[3*i+1], means[3*i+2],
                                    __int_as_float(i));
        g_icov_s[pos] = make_float4(expf(-logc[3*i]), expf(-logc[3*i+1]),
                                    expf(-logc[3*i+2]), 0.f);
    }
    if (i < M) {
        int pos = g_qstart[g_qcell[i]] + g_qrank[i];
        g_qorder[pos] = i;
    }
}

// Exact per-query fallback (rare): gmem ring expansion + threshold rescan.
__device__ __noinline__ void fallback_query(int q, float qx, float qy, float qz,
                                            int cx, int cy, int cz,
                                            const float4* __restrict__ feats4,
                                            float* __restrict__ out) {
    const float h = 1.0f / (float)G;
    float bd[KNN];
#pragma unroll
    for (int t = 0; t < KNN; t++) bd[t] = FLT_MAX;

    int rfin = 1;
    for (int r = 1; r <= G; ++r) {
        rfin = r;
        for (int dz = -r; dz <= r; ++dz) {
            int z = cz + dz; if ((unsigned)z >= G) continue;
            for (int dy = -r; dy <= r; ++dy) {
                int y = cy + dy; if ((unsigned)y >= G) continue;
                bool edge = (dz == -r) | (dz == r) | (dy == -r) | (dy == r);
                int step = (r > 1 && !edge) ? 2 * r : 1;
                for (int dx = -r; dx <= r; dx += step) {
                    int x = cx + dx; if ((unsigned)x >= G) continue;
                    int cid = (z * G + y) * G + x;
                    int c0 = g_start[cid], c1 = g_start[cid + 1];
                    for (int c = c0; c < c1; ++c) {
                        float4 g = g_sorted[c];
                        float ddx = qx - g.x, ddy = qy - g.y, ddz = qz - g.z;
                        float d2 = fmaf(ddx, ddx, fmaf(ddy, ddy, ddz * ddz));
                        if (d2 < bd[0]) {
                            bd[0] = d2;
#pragma unroll
                            for (int t = 0; t < KNN - 1; t++) {
                                float a = fmaxf(bd[t], bd[t+1]);
                                float b = fminf(bd[t], bd[t+1]);
                                bd[t] = a; bd[t+1] = b;
                            }
                        }
                    }
                }
            }
        }
        float m = 1e30f;
        if (cx - r > 0)     m = fminf(m, qx - (float)(cx - r) * h);
        if (cx + r < G - 1) m = fminf(m, (float)(cx + r + 1) * h - qx);
        if (cy - r > 0)     m = fminf(m, qy - (float)(cy - r) * h);
        if (cy + r < G - 1) m = fminf(m, (float)(cy + r + 1) * h - qy);
        if (cz - r > 0)     m = fminf(m, qz - (float)(cz - r) * h);
        if (cz + r < G - 1) m = fminf(m, (float)(cz + r + 1) * h - qz);
        if (bd[0] <= m * m) break;
    }
    const float T = bd[0];

    int myp[KNN];
#pragma unroll
    for (int t = 0; t < KNN; t++) myp[t] = 0;
    int cnt = 0;
    {
        const int r = rfin;
        for (int dz = -r; dz <= r; ++dz) {
            int z = cz + dz; if ((unsigned)z >= G) continue;
            for (int dy = -r; dy <= r; ++dy) {
                int y = cy + dy; if ((unsigned)y >= G) continue;
                for (int dx = -r; dx <= r; ++dx) {
                    int x = cx + dx; if ((unsigned)x >= G) continue;
                    int cid = (z * G + y) * G + x;
                    int c0 = g_start[cid], c1 = g_start[cid + 1];
                    for (int c = c0; c < c1; ++c) {
                        float4 g = g_sorted[c];
                        float ddx = qx - g.x, ddy = qy - g.y, ddz = qz - g.z;
                        float d2 = fmaf(ddx, ddx, fmaf(ddy, ddy, ddz * ddz));
                        if (d2 <= T && cnt < KNN) { myp[cnt] = c; cnt++; }
                    }
                }
            }
        }
    }

    float acc[NF];
#pragma unroll
    for (int f = 0; f < NF; f++) acc[f] = 0.f;
    float wsum = 0.f;
#pragma unroll
    for (int t = 0; t < KNN; t++) {
        int p = myp[t];
        float4 g = g_sorted[p];
        float4 ic = g_icov_s[p];
        int id = __float_as_int(g.w);
        float ddx = qx - g.x, ddy = qy - g.y, ddz = qz - g.z;
        float e = fmaf(ddx*ddx, ic.x, fmaf(ddy*ddy, ic.y, ddz*ddz*ic.z));
        float wgt = __expf(-0.5f * e);
        wsum += wgt;
        const float4* fp = feats4 + (size_t)id * (NF/4);
#pragma unroll
        for (int cc = 0; cc < NF/4; cc++) {
            float4 fv = fp[cc];
            acc[4*cc+0] = fmaf(wgt, fv.x, acc[4*cc+0]);
            acc[4*cc+1] = fmaf(wgt, fv.y, acc[4*cc+1]);
            acc[4*cc+2] = fmaf(wgt, fv.z, acc[4*cc+2]);
            acc[4*cc+3] = fmaf(wgt, fv.w, acc[4*cc+3]);
        }
    }
    float inv = 1.f / (wsum + 1e-8f);
    float4* o4 = (float4*)(out + (size_t)q * NF);
#pragma unroll
    for (int cc = 0; cc < NF/4; cc++)
        o4[cc] = make_float4(acc[4*cc+0]*inv, acc[4*cc+1]*inv,
                             acc[4*cc+2]*inv, acc[4*cc+3]*inv);
}

// Main: one block per cell. Radially-sorted window built in SMEM, then
// 4 lanes/query scan (LDS broadcast), exact quad merge, per-lane epilogue.
__global__ __launch_bounds__(256, 4)
void splash_cell(const float* __restrict__ coords,
                 const float4* __restrict__ feats4,
                 float* __restrict__ out) {
    __shared__ float4 sstage[WMAX];          // staged positions (build)
    __shared__ float  skey[WMAX];
    __shared__ int    sgid[WMAX];
    __shared__ float4 spos[CAPW];            // window positions (x,y,z,|m|^2+3)
    __shared__ float4 sicv[CAPW];            // window icov (.w = orig id bits)
    __shared__ float  scd[CAPW + 32];        // center-dist^2 (+slack)
    __shared__ int    cnt[NBKT], st[NBKT + 1], fil[NBKT];
    __shared__ int    rr0[9], roff[10], rcnt_s;
    __shared__ int    nsw_s, nswp_s;
    __shared__ float  wmarg_s;

    const int cell = blockIdx.x;
    const int q0 = g_qstart[cell], q1 = g_qstart[cell + 1];
    if (q0 == q1) return;
    const int tid = threadIdx.x;

    // ---- window build (bucket counting-sort by center distance) ----
    const int cx = cell & 7, cy = (cell >> 3) & 7, cz = cell >> 6;
    const float ccx = (cx + 0.5f) * 0.125f;
    const float ccy = (cy + 0.5f) * 0.125f;
    const float ccz = (cz + 0.5f) * 0.125f;

    if (tid < NBKT) { cnt[tid] = 0; fil[tid] = 0; }
    const int x0 = max(cx - 1, 0), x1e = min(cx + 1, G - 1) + 1;
    if (tid == 0) {
        int rc = 0, n0 = 0;
        for (int z = max(cz - 1, 0); z <= min(cz + 1, G - 1); ++z) {
            for (int y = max(cy - 1, 0); y <= min(cy + 1, G - 1); ++y) {
                int base = (z * G + y) * G;
                int r0 = g_start[base + x0];
                int len = g_start[base + x1e] - r0;
                rr0[rc] = r0; roff[rc] = n0;
                n0 += len; rc++;
            }
        }
        roff[rc] = n0;
        rcnt_s = rc;
    }
    __syncthreads();

    const int rcnt = rcnt_s;
    const int n = roff[rcnt];
    const bool ovf = (n > WMAX);

    if (!ovf) {
        for (int i = tid; i < n; i += 256) {
            int k = 0;
#pragma unroll
            for (int kk = 1; kk < 9; kk++)
                if (kk < rcnt && i >= roff[kk]) k = kk;
            int src = rr0[k] + (i - roff[k]);
            float4 g = g_sorted[src];
            float dx = g.x - ccx, dy = g.y - ccy, dz = g.z - ccz;
            float cd = fmaf(dx, dx, fmaf(dy, dy, dz * dz));
            sstage[i] = g;
            skey[i] = cd;
            sgid[i] = src;
            atomicAdd(&cnt[min(NBKT - 1, (int)(cd * INVBW))], 1);
        }
    }
    __syncthreads();

    if (tid < 32) {
        int v = cnt[tid];
        for (int o = 1; o < 32; o <<= 1) {
            int u = __shfl_up_sync(0xffffffffu, v, o);
            if (tid >= o) v += u;
        }
        st[tid + 1] = v;
        if (tid == 0) st[0] = 0;
    }
    __syncthreads();

    if (tid == 0) {
        int nsw = ovf ? 0 : min(n, CAPW);
        float marg = 1e30f;
        if (ovf) marg = -1.f;
        else if (n > CAPW) {
            int t = 0;
            while (t < NBKT && st[t + 1] <= CAPW) t++;
            marg = (float)t * BWIDTH;
        }
        nsw_s = nsw;
        nswp_s = min(CAPW, (nsw + 31) & ~31);
        wmarg_s = marg;
    }
    __syncthreads();

    const int nSW = nsw_s, nSWP = nswp_s;
    const float wmarg = wmarg_s;

    if (!ovf) {
        for (int i = tid; i < n; i += 256) {
            float cd = skey[i];
            int b = min(NBKT - 1, (int)(cd * INVBW));
            int pos = st[b] + atomicAdd(&fil[b], 1);
            if (pos < CAPW) {
                float4 gp = sstage[i];
                float m2 = fmaf(gp.x, gp.x, fmaf(gp.y, gp.y, gp.z * gp.z)) + 3.f;
                spos[pos] = make_float4(gp.x, gp.y, gp.z, m2);
                float4 ic = g_icov_s[sgid[i]];
                sicv[pos] = make_float4(ic.x, ic.y, ic.z, gp.w);
                scd[pos] = cd;
            }
        }
        for (int i = nSW + tid; i < nSWP; i += 256) {
            spos[i] = make_float4(64.f, 64.f, 64.f, 3.f * 64.f * 64.f + 3.f);
            sicv[i] = make_float4(0.f, 0.f, 0.f, __int_as_float(0));
            scd[i] = 1e30f;
        }
    }
    __syncthreads();

    // ---- query processing: 4 lanes/query, quads strided over the cell ----
    const int lane = tid & 31;
    const int L = lane & 3;
    const int quad = tid >> 2;          // 0..63
    const float h = 0.125f;
    const int nq = q1 - q0;
    const int nrounds = (nq + 63) >> 6;

    for (int rr = 0; rr < nrounds; rr++) {
        const int qi = q0 + quad + (rr << 6);
        const bool has = qi < q1;
        const int q = g_qorder[has ? qi : q0];
        const float qx = coords[3*q+0], qy = coords[3*q+1], qz = coords[3*q+2];
        const float qq = fmaf(qx, qx, fmaf(qy, qy, qz * qz));
        const float n2x = -2.f * qx, n2y = -2.f * qy, n2z = -2.f * qz;
        float rdx = qx - ccx, rdy = qy - ccy, rdz = qz - ccz;
        const float rq = sqrtf(fmaf(rdx, rdx, fmaf(rdy, rdy, rdz * rdz)));

        const bool mainable = has && nSW >= 32 && wmarg >= 0.f;

        unsigned key[KD];
#pragma unroll
        for (int t = 0; t < KD; t++) key[t] = 0xFFFFFFFFu;

        bool done = !mainable;
        for (int base = 0; !__all_sync(0xffffffffu, done); base += 32) {
            if (!done) {
                float ncd = scd[base + 32];
                float tv[8];
#pragma unroll
                for (int k = 0; k < 8; k++) {
                    float4 g = spos[base + L + 4 * k];
                    tv[k] = fmaf(g.x, n2x, fmaf(g.y, n2y, fmaf(g.z, n2z, g.w)));
                }
#pragma unroll
                for (int k = 0; k < 8; k++) {
                    int j = base + L + 4 * k;
                    unsigned kn = (__float_as_uint(tv[k]) & ~IDXMASK) | (unsigned)j;
                    if (kn < key[0]) {
                        key[0] = kn;
#pragma unroll
                        for (int s = 0; s < KD - 1; s++) {
                            unsigned a = umax(key[s], key[s+1]);
                            unsigned b = umin(key[s], key[s+1]);
                            key[s] = a; key[s+1] = b;
                        }
                    }
                }
                if (base + 32 >= nSWP) done = true;
                else {
                    float d16sq = __uint_as_float(key[0] & ~IDXMASK) - 3.f + qq;
                    if (d16sq >= 0.f) {
                        float dn = sqrtf(d16sq) + rq;
                        if (ncd - BWIDTH > dn * dn) done = true;
                    }
                }
            }
        }

        // Two-stage exact quad merge (pads inlined: slots 0..3 are +inf).
#define PK_(i) ((i) < 4 ? 0xFFFFFFFFu : key[(i) - 4])
        unsigned e[16];
#pragma unroll
        for (int t = 0; t < 16; t++) {
            unsigned pp = __shfl_xor_sync(0xffffffffu, PK_(15 - t), 1);
            e[t] = umin(PK_(t), pp);
        }
#undef PK_
#define CE_(i, j) { unsigned a_ = umax(e[i], e[j]); unsigned b_ = umin(e[i], e[j]); e[i] = a_; e[j] = b_; }
#pragma unroll
        for (int i = 0; i < 8; i++) CE_(i, i + 8);
#pragma unroll
        for (int hb = 0; hb < 16; hb += 8)
#pragma unroll
            for (int i = 0; i < 4; i++) CE_(hb + i, hb + i + 4);
#pragma unroll
        for (int hb = 0; hb < 16; hb += 4)
#pragma unroll
            for (int i = 0; i < 2; i++) CE_(hb + i, hb + i + 2);
#pragma unroll
        for (int i = 0; i < 16; i += 2) CE_(i, i + 1);
#undef CE_

        unsigned gk[16];
#pragma unroll
        for (int t = 0; t < 16; t++) {
            unsigned pp = __shfl_xor_sync(0xffffffffu, e[15 - t], 2);
            gk[t] = umin(e[t], pp);
        }
        unsigned mx = gk[0];
#pragma unroll
        for (int t = 1; t < 16; t++) mx = umax(mx, gk[t]);

        bool lane_ok = (key[0] >= mx);
        unsigned bal = __ballot_sync(0xffffffffu, lane_ok);
        bool quad_ok = (((bal >> (lane & ~3)) & 0xFu) == 0xFu);

        float d16sq = __uint_as_float(mx & ~IDXMASK) - 3.f + qq;
        float m = 1e30f;
        if (cx - 1 > 0)     m = fminf(m, qx - (float)(cx - 1) * h);
        if (cx + 1 < G - 1) m = fminf(m, (float)(cx + 2) * h - qx);
        if (cy - 1 > 0)     m = fminf(m, qy - (float)(cy - 1) * h);
        if (cy + 1 < G - 1) m = fminf(m, (float)(cy + 2) * h - qy);
        if (cz - 1 > 0)     m = fminf(m, qz - (float)(cz - 1) * h);
        if (cz + 1 < G - 1) m = fminf(m, (float)(cz + 2) * h - qz);

        float d16c = sqrtf(fmaxf(d16sq, 0.f));
        bool ok = mainable && quad_ok && (d16sq <= m * m)
                  && ((d16c + rq) * (d16c + rq) <= wmarg);

        if (has && !ok && L == 0)
            fallback_query(q, qx, qy, qz, cx, cy, cz, feats4, out);

        if (has && ok) {
            float acc[NF/4];
#pragma unroll
            for (int f = 0; f < NF/4; f++) acc[f] = 0.f;
            float wsum = 0.f;
#pragma unroll
            for (int t = 0; t < KNN; t++) {
                int p = (int)(gk[t] & IDXMASK);
                float4 g = spos[p];
                float4 ic = sicv[p];
                int id = __float_as_int(ic.w);
                float ddx = qx - g.x, ddy = qy - g.y, ddz = qz - g.z;
                float e2 = fmaf(ddx*ddx, ic.x, fmaf(ddy*ddy, ic.y, ddz*ddz*ic.z));
                float wgt = __expf(-0.5f * e2);
                wsum += wgt;
                const float4* fp = feats4 + (size_t)id * (NF/4) + L * 2;
                float4 f0 = __ldg(&fp[0]);
                float4 f1 = __ldg(&fp[1]);
                acc[0] = fmaf(wgt, f0.x, acc[0]);
                acc[1] = fmaf(wgt, f0.y, acc[1]);
                acc[2] = fmaf(wgt, f0.z, acc[2]);
                acc[3] = fmaf(wgt, f0.w, acc[3]);
                acc[4] = fmaf(wgt, f1.x, acc[4]);
                acc[5] = fmaf(wgt, f1.y, acc[5]);
                acc[6] = fmaf(wgt, f1.z, acc[6]);
                acc[7] = fmaf(wgt, f1.w, acc[7]);
            }
            float inv = 1.f / (wsum + 1e-8f);
            float4* o4 = (float4*)(out + (size_t)q * NF) + L * 2;
            o4[0] = make_float4(acc[0]*inv, acc[1]*inv, acc[2]*inv, acc[3]*inv);
            o4[1] = make_float4(acc[4]*inv, acc[5]*inv, acc[6]*inv, acc[7]*inv);
        }
    }
}

extern "C" void kernel_launch(void* const* d_in, const int* in_sizes, int n_in,
                              void* d_out, int out_size) {
    const float* coords = (const float*)d_in[0];
    const float* means  = (const float*)d_in[1];
    const float* logc   = (const float*)d_in[2];
    const float* feats  = (const float*)d_in[3];
    float* out = (float*)d_out;

    int M = in_sizes[0] / 3;
    int N = in_sizes[1] / 3;
    int mx = (M > N ? M : N);

    k_hist<<<(mx + 255) / 256, 256>>>(means, N, coords, M);
    k_scatter<<<(mx + 255) / 256, 256>>>(means, logc, N, M);
    splash_cell<<<NC, 256>>>(coords, (const float4*)feats, out);
}

// round 15
// speedup vs baseline: 1.7608x; 1.0610x over previous
#include <cuda_runtime.h>
#include <math.h>
#include <float.h>

#define G 8
#define NC (G*G*G)
#define GQ 16
#define NCQ (GQ*GQ*GQ)      // 4096 query-ordering cells
#define MAXN 10016
#define MAXM 32768
#define KNN 16
#define NF 32
#define CAPW 512
#define WMAX 1024
#define NBKT 32
#define KD 12
#define IDXMASK 0x1FFu
#define CDMAX 0.1055f
#define BWIDTH (CDMAX / (float)NBKT)
#define INVBW ((float)NBKT / CDMAX)

// ---- device scratch (allocation-free) ----
__device__ float4 g_sorted[MAXN];      // cell-ordered: (x,y,z, orig-idx bits)
__device__ float4 g_icov_o[MAXN];      // inverse covariances, ORIGINAL order
__device__ int g_cnt[NC], g_start[NC + 1];
__device__ int g_qcnt[NCQ], g_qstart[NCQ + 1];
__device__ int g_gcell[MAXN], g_grank[MAXN];
__device__ int g_qcell[MAXM], g_qrank[MAXM];
__device__ int g_qorder[MAXM];
__device__ int g_done;
__device__ float4 g_winpos[NC * CAPW + 32]; // (x,y,z, |m|^2+3); pads sentinel
__device__ int    g_winid[NC * CAPW + 32];  // original gaussian id
__device__ float  g_wincd[NC * CAPW + 32];  // center-dist^2 (+slack)
__device__ float  g_wmargin[NC];
__device__ int    g_nsw[NC];
__device__ int    g_nswp[NC];

__device__ __forceinline__ int cell_coord(float v) {
    int c = (int)(v * (float)G);
    return min(G - 1, max(0, c));
}
__device__ __forceinline__ int cell16(float v) {
    int c = (int)(v * (float)GQ);
    return min(GQ - 1, max(0, c));
}

// 512-entry exclusive scan (2/thread); zeroes src.
__device__ void scan512_zero(int* src, int* dst) {
    __shared__ int ws[8];
    int t = threadIdx.x, lane = t & 31, w = t >> 5;
    int c0 = src[2 * t], c1 = src[2 * t + 1];
    src[2 * t] = 0; src[2 * t + 1] = 0;
    int s = c0 + c1;
    int v = s;
    for (int o = 1; o < 32; o <<= 1) {
        int u = __shfl_up_sync(0xffffffffu, v, o);
        if (lane >= o) v += u;
    }
    if (lane == 31) ws[w] = v;
    __syncthreads();
    if (t < 32) {
        int p = (t < 8) ? ws[t] : 0;
        for (int o = 1; o < 8; o <<= 1) {
            int u = __shfl_up_sync(0xffffffffu, p, o);
            if (t >= o) p += u;
        }
        if (t < 8) ws[t] = p;
    }
    __syncthreads();
    int incl = v + (w ? ws[w - 1] : 0);
    int excl = incl - s;
    dst[2 * t + 1] = excl + c0;
    dst[2 * t + 2] = incl;
    if (t == 0) dst[0] = 0;
    __syncthreads();
}

// 4096-entry exclusive scan (16/thread); zeroes src.
__device__ void scan4096_zero(int* src, int* dst) {
    __shared__ int ws2[8];
    int t = threadIdx.x, lane = t & 31, w = t >> 5;
    int v[16];
    int s = 0;
#pragma unroll
    for (int k = 0; k < 16; k++) {
        v[k] = src[t * 16 + k];
        src[t * 16 + k] = 0;
        s += v[k];
    }
    int run = 0;
#pragma unroll
    for (int k = 0; k < 16; k++) { run += v[k]; v[k] = run; }   // inclusive
    int ss = s;
    for (int o = 1; o < 32; o <<= 1) {
        int u = __shfl_up_sync(0xffffffffu, ss, o);
        if (lane >= o) ss += u;
    }
    if (lane == 31) ws2[w] = ss;
    __syncthreads();
    if (t < 32) {
        int p = (t < 8) ? ws2[t] : 0;
        for (int o = 1; o < 8; o <<= 1) {
            int u = __shfl_up_sync(0xffffffffu, p, o);
            if (t >= o) p += u;
        }
        if (t < 8) ws2[t] = p;
    }
    __syncthreads();
    int base = ss - s + (w ? ws2[w - 1] : 0);
#pragma unroll
    for (int k = 0; k < 16; k++) dst[t * 16 + k + 1] = base + v[k];
    if (t == 0) dst[0] = 0;
    __syncthreads();
}

// Histogram + icov precompute + (last block) both scans. No __threadfence:
// counters are only mutated by atomicAdd-with-return (complete at L2) and
// the scanning block never cached those lines in L1.
__global__ void k_hist(const float* __restrict__ means,
                       const float* __restrict__ logc, int N,
                       const float* __restrict__ coords, int M) {
    int i = blockIdx.x * blockDim.x + threadIdx.x;
    if (i < N) {
        int c = (cell_coord(means[3*i+2]) * G + cell_coord(means[3*i+1])) * G
                + cell_coord(means[3*i+0]);
        g_gcell[i] = c;
        g_grank[i] = atomicAdd(&g_cnt[c], 1);
        g_icov_o[i] = make_float4(expf(-logc[3*i]), expf(-logc[3*i+1]),
                                  expf(-logc[3*i+2]), 0.f);
    }
    if (i < M) {
        int c = (cell16(coords[3*i+2]) * GQ + cell16(coords[3*i+1])) * GQ
                + cell16(coords[3*i+0]);
        g_qcell[i] = c;
        g_qrank[i] = atomicAdd(&g_qcnt[c], 1);
    }
    __syncthreads();
    __shared__ int is_last;
    if (threadIdx.x == 0) {
        int prev = atomicAdd(&g_done, 1);
        is_last = (prev == (int)gridDim.x - 1);
    }
    __syncthreads();
    if (!is_last) return;
    if (threadIdx.x == 0) g_done = 0;
    scan512_zero(g_cnt, g_start);
    scan4096_zero(g_qcnt, g_qstart);
}

__global__ void k_scatter(const float* __restrict__ means, int N, int M) {
    int i = blockIdx.x * blockDim.x + threadIdx.x;
    if (i < N) {
        int pos = g_start[g_gcell[i]] + g_grank[i];
        g_sorted[pos] = make_float4(means[3*i], means[3*i+1], means[3*i+2],
                                    __int_as_float(i));
    }
    if (i < M) {
        int pos = g_qstart[g_qcell[i]] + g_qrank[i];
        g_qorder[pos] = i;
    }
}

// Per-cell radially-ordered window (bucket counting sort by center dist).
__global__ __launch_bounds__(256)
void k_window() {
    __shared__ float4 spos4[WMAX];
    __shared__ float  skey[WMAX];
    __shared__ int    cnt[NBKT], st[NBKT + 1], fil[NBKT];
    __shared__ int    rr0[9], roff[10], rcnt_s;

    const int cell = blockIdx.x, tid = threadIdx.x;
    const int cx = cell & 7, cy = (cell >> 3) & 7, cz = cell >> 6;
    const float ccx = (cx + 0.5f) * 0.125f;
    const float ccy = (cy + 0.5f) * 0.125f;
    const float ccz = (cz + 0.5f) * 0.125f;

    if (tid < NBKT) { cnt[tid] = 0; fil[tid] = 0; }

    const int x0 = max(cx - 1, 0), x1e = min(cx + 1, G - 1) + 1;
    if (tid == 0) {
        int rc = 0, n0 = 0;
        for (int z = max(cz - 1, 0); z <= min(cz + 1, G - 1); ++z) {
            for (int y = max(cy - 1, 0); y <= min(cy + 1, G - 1); ++y) {
                int base = (z * G + y) * G;
                int r0 = g_start[base + x0];
                int len = g_start[base + x1e] - r0;
                rr0[rc] = r0; roff[rc] = n0;
                n0 += len; rc++;
            }
        }
        roff[rc] = n0;
        rcnt_s = rc;
    }
    __syncthreads();

    const int rcnt = rcnt_s;
    const int n = roff[rcnt];
    const bool ovf = (n > WMAX);

    if (!ovf) {
        for (int i = tid; i < n; i += 256) {
            int k = 0;
#pragma unroll
            for (int kk = 1; kk < 9; kk++)
                if (kk < rcnt && i >= roff[kk]) k = kk;
            int src = rr0[k] + (i - roff[k]);
            float4 g = g_sorted[src];
            float dx = g.x - ccx, dy = g.y - ccy, dz = g.z - ccz;
            float cd = fmaf(dx, dx, fmaf(dy, dy, dz * dz));
            spos4[i] = g;
            skey[i] = cd;
            atomicAdd(&cnt[min(NBKT - 1, (int)(cd * INVBW))], 1);
        }
    }
    __syncthreads();

    if (tid < 32) {
        int v = cnt[tid];
        for (int o = 1; o < 32; o <<= 1) {
            int u = __shfl_up_sync(0xffffffffu, v, o);
            if (tid >= o) v += u;
        }
        st[tid + 1] = v;
        if (tid == 0) st[0] = 0;
    }
    __syncthreads();

    int nsw = min(n, CAPW);
    if (ovf) nsw = 0;
    const int nswp = min(CAPW, (nsw + 31) & ~31);

    if (tid == 0) {
        float marg = 1e30f;
        if (ovf) marg = -1.f;
        else if (n > CAPW) {
            int t = 0;
            while (t < NBKT && st[t + 1] <= CAPW) t++;
            marg = (float)t * BWIDTH;
        }
        g_wmargin[cell] = marg;
        g_nsw[cell] = nsw;
        g_nswp[cell] = nswp;
    }
    __syncthreads();

    if (!ovf) {
        for (int i = tid; i < n; i += 256) {
            float cd = skey[i];
            int b = min(NBKT - 1, (int)(cd * INVBW));
            int pos = st[b] + atomicAdd(&fil[b], 1);
            if (pos < CAPW) {
                float4 gp = spos4[i];
                float m2 = fmaf(gp.x, gp.x, fmaf(gp.y, gp.y, gp.z * gp.z)) + 3.f;
                g_winpos[cell * CAPW + pos] = make_float4(gp.x, gp.y, gp.z, m2);
                g_winid[cell * CAPW + pos] = __float_as_int(gp.w);
                g_wincd[cell * CAPW + pos] = cd;
            }
        }
        for (int i = nsw + tid; i < nswp; i += 256) {
            g_winpos[cell * CAPW + i] = make_float4(64.f, 64.f, 64.f,
                                                    3.f * 64.f * 64.f + 3.f);
            g_winid[cell * CAPW + i] = 0;
            g_wincd[cell * CAPW + i] = 1e30f;
        }
    }
}

// Exact per-query fallback (rare).
__device__ __noinline__ void fallback_query(int q, float qx, float qy, float qz,
                                            int cx, int cy, int cz,
                                            const float4* __restrict__ feats4,
                                            float* __restrict__ out) {
    const float h = 1.0f / (float)G;
    float bd[KNN];
#pragma unroll
    for (int t = 0; t < KNN; t++) bd[t] = FLT_MAX;

    int rfin = 1;
    for (int r = 1; r <= G; ++r) {
        rfin = r;
        for (int dz = -r; dz <= r; ++dz) {
            int z = cz + dz; if ((unsigned)z >= G) continue;
            for (int dy = -r; dy <= r; ++dy) {
                int y = cy + dy; if ((unsigned)y >= G) continue;
                bool edge = (dz == -r) | (dz == r) | (dy == -r) | (dy == r);
                int step = (r > 1 && !edge) ? 2 * r : 1;
                for (int dx = -r; dx <= r; dx += step) {
                    int x = cx + dx; if ((unsigned)x >= G) continue;
                    int cid = (z * G + y) * G + x;
                    int c0 = g_start[cid], c1 = g_start[cid + 1];
                    for (int c = c0; c < c1; ++c) {
                        float4 g = g_sorted[c];
                        float ddx = qx - g.x, ddy = qy - g.y, ddz = qz - g.z;
                        float d2 = fmaf(ddx, ddx, fmaf(ddy, ddy, ddz * ddz));
                        if (d2 < bd[0]) {
                            bd[0] = d2;
#pragma unroll
                            for (int t = 0; t < KNN - 1; t++) {
                                float a = fmaxf(bd[t], bd[t+1]);
                                float b = fminf(bd[t], bd[t+1]);
                                bd[t] = a; bd[t+1] = b;
                            }
                        }
                    }
                }
            }
        }
        float m = 1e30f;
        if (cx - r > 0)     m = fminf(m, qx - (float)(cx - r) * h);
        if (cx + r < G - 1) m = fminf(m, (float)(cx + r + 1) * h - qx);
        if (cy - r > 0)     m = fminf(m, qy - (float)(cy - r) * h);
        if (cy + r < G - 1) m = fminf(m, (float)(cy + r + 1) * h - qy);
        if (cz - r > 0)     m = fminf(m, qz - (float)(cz - r) * h);
        if (cz + r < G - 1) m = fminf(m, (float)(cz + r + 1) * h - qz);
        if (bd[0] <= m * m) break;
    }
    const float T = bd[0];

    int myp[KNN];
#pragma unroll
    for (int t = 0; t < KNN; t++) myp[t] = 0;
    int cnt = 0;
    {
        const int r = rfin;
        for (int dz = -r; dz <= r; ++dz) {
            int z = cz + dz; if ((unsigned)z >= G) continue;
            for (int dy = -r; dy <= r; ++dy) {
                int y = cy + dy; if ((unsigned)y >= G) continue;
                for (int dx = -r; dx <= r; ++dx) {
                    int x = cx + dx; if ((unsigned)x >= G) continue;
                    int cid = (z * G + y) * G + x;
                    int c0 = g_start[cid], c1 = g_start[cid + 1];
                    for (int c = c0; c < c1; ++c) {
                        float4 g = g_sorted[c];
                        float ddx = qx - g.x, ddy = qy - g.y, ddz = qz - g.z;
                        float d2 = fmaf(ddx, ddx, fmaf(ddy, ddy, ddz * ddz));
                        if (d2 <= T && cnt < KNN) { myp[cnt] = c; cnt++; }
                    }
                }
            }
        }
    }

    float acc[NF];
#pragma unroll
    for (int f = 0; f < NF; f++) acc[f] = 0.f;
    float wsum = 0.f;
#pragma unroll
    for (int t = 0; t < KNN; t++) {
        int p = myp[t];
        float4 g = g_sorted[p];
        int id = __float_as_int(g.w);
        float4 ic = g_icov_o[id];
        float ddx = qx - g.x, ddy = qy - g.y, ddz = qz - g.z;
        float e = fmaf(ddx*ddx, ic.x, fmaf(ddy*ddy, ic.y, ddz*ddz*ic.z));
        float wgt = __expf(-0.5f * e);
        wsum += wgt;
        const float4* fp = feats4 + (size_t)id * (NF/4);
#pragma unroll
        for (int cc = 0; cc < NF/4; cc++) {
            float4 fv = fp[cc];
            acc[4*cc+0] = fmaf(wgt, fv.x, acc[4*cc+0]);
            acc[4*cc+1] = fmaf(wgt, fv.y, acc[4*cc+1]);
            acc[4*cc+2] = fmaf(wgt, fv.z, acc[4*cc+2]);
            acc[4*cc+3] = fmaf(wgt, fv.w, acc[4*cc+3]);
        }
    }
    float inv = 1.f / (wsum + 1e-8f);
    float4* o4 = (float4*)(out + (size_t)q * NF);
#pragma unroll
    for (int cc = 0; cc < NF/4; cc++)
        o4[cc] = make_float4(acc[4*cc+0]*inv, acc[4*cc+1]*inv,
                             acc[4*cc+2]*inv, acc[4*cc+3]*inv);
}

// Main: 4 lanes/query, 8 queries/warp (sub-cell-sorted -> coherent warps),
// padded windows, prefetched early exit.
__global__ __launch_bounds__(128, 7)
void splash_q(const float* __restrict__ coords,
              const float4* __restrict__ feats4,
              float* __restrict__ out, int M) {
    const int gw = (blockIdx.x * blockDim.x + threadIdx.x) >> 5;
    const int lane = threadIdx.x & 31;
    const int L = lane & 3;
    const int qslot = gw * 8 + (lane >> 2);
    const bool has = qslot < M;

    const int q = g_qorder[has ? qslot : 0];
    const float qx = coords[3*q+0], qy = coords[3*q+1], qz = coords[3*q+2];
    const int cx = cell_coord(qx), cy = cell_coord(qy), cz = cell_coord(qz);
    const int cell = (cz * G + cy) * G + cx;
    const int cb = cell * CAPW;
    const int nSW = g_nsw[cell];
    const int nSWP = g_nswp[cell];
    const float wmarg = g_wmargin[cell];

    const float qq = fmaf(qx, qx, fmaf(qy, qy, qz * qz));
    const float n2x = -2.f * qx, n2y = -2.f * qy, n2z = -2.f * qz;
    const float ccx = (cx + 0.5f) * 0.125f;
    const float ccy = (cy + 0.5f) * 0.125f;
    const float ccz = (cz + 0.5f) * 0.125f;
    float rdx = qx - ccx, rdy = qy - ccy, rdz = qz - ccz;
    const float rq = sqrtf(fmaf(rdx, rdx, fmaf(rdy, rdy, rdz * rdz)));

    const bool mainable = has && nSW >= 32 && wmarg >= 0.f;

    unsigned key[KD];
#pragma unroll
    for (int t = 0; t < KD; t++) key[t] = 0xFFFFFFFFu;

    bool done = !mainable;
    for (int base = 0; !__all_sync(0xffffffffu, done); base += 32) {
        if (!done) {
            float ncd = __ldg(&g_wincd[cb + base + 32]);
            float tv[8];
#pragma unroll
            for (int k = 0; k < 8; k++) {
                float4 g = __ldg(&g_winpos[cb + base + L + 4 * k]);
                tv[k] = fmaf(g.x, n2x, fmaf(g.y, n2y, fmaf(g.z, n2z, g.w)));
            }
#pragma unroll
            for (int k = 0; k < 8; k++) {
                int j = base + L + 4 * k;
                unsigned kn = (__float_as_uint(tv[k]) & ~IDXMASK) | (unsigned)j;
                if (kn < key[0]) {
                    key[0] = kn;
#pragma unroll
                    for (int s = 0; s < KD - 1; s++) {
                        unsigned a = umax(key[s], key[s+1]);
                        unsigned b = umin(key[s], key[s+1]);
                        key[s] = a; key[s+1] = b;
                    }
                }
            }
            if (base + 32 >= nSWP) done = true;
            else {
                float d16sq = __uint_as_float(key[0] & ~IDXMASK) - 3.f + qq;
                if (d16sq >= 0.f) {
                    float dn = sqrtf(d16sq) + rq;
                    if (ncd - BWIDTH > dn * dn) done = true;
                }
            }
        }
    }

    // Two-stage exact quad merge (pads inlined: slots 0..3 are +inf).
#define PK_(i) ((i) < 4 ? 0xFFFFFFFFu : key[(i) - 4])
    unsigned e[16];
#pragma unroll
    for (int t = 0; t < 16; t++) {
        unsigned pp = __shfl_xor_sync(0xffffffffu, PK_(15 - t), 1);
        e[t] = umin(PK_(t), pp);
    }
#undef PK_
#define CE_(i, j) { unsigned a_ = umax(e[i], e[j]); unsigned b_ = umin(e[i], e[j]); e[i] = a_; e[j] = b_; }
#pragma unroll
    for (int i = 0; i < 8; i++) CE_(i, i + 8);
#pragma unroll
    for (int hb = 0; hb < 16; hb += 8)
#pragma unroll
        for (int i = 0; i < 4; i++) CE_(hb + i, hb + i + 4);
#pragma unroll
    for (int hb = 0; hb < 16; hb += 4)
#pragma unroll
        for (int i = 0; i < 2; i++) CE_(hb + i, hb + i + 2);
#pragma unroll
    for (int i = 0; i < 16; i += 2) CE_(i, i + 1);
#undef CE_

    unsigned gk[16];
#pragma unroll
    for (int t = 0; t < 16; t++) {
        unsigned pp = __shfl_xor_sync(0xffffffffu, e[15 - t], 2);
        gk[t] = umin(e[t], pp);
    }
    unsigned mx = gk[0];
#pragma unroll
    for (int t = 1; t < 16; t++) mx = umax(mx, gk[t]);

    bool lane_ok = (key[0] >= mx);
    unsigned bal = __ballot_sync(0xffffffffu, lane_ok);
    bool quad_ok = (((bal >> (lane & ~3)) & 0xFu) == 0xFu);

    float d16sq = __uint_as_float(mx & ~IDXMASK) - 3.f + qq;
    const float h = 0.125f;
    float m = 1e30f;
    if (cx - 1 > 0)     m = fminf(m, qx - (float)(cx - 1) * h);
    if (cx + 1 < G - 1) m = fminf(m, (float)(cx + 2) * h - qx);
    if (cy - 1 > 0)     m = fminf(m, qy - (float)(cy - 1) * h);
    if (cy + 1 < G - 1) m = fminf(m, (float)(cy + 2) * h - qy);
    if (cz - 1 > 0)     m = fminf(m, qz - (float)(cz - 1) * h);
    if (cz + 1 < G - 1) m = fminf(m, (float)(cz + 2) * h - qz);

    float d16c = sqrtf(fmaxf(d16sq, 0.f));
    bool ok = mainable && quad_ok && (d16sq <= m * m)
              && ((d16c + rq) * (d16c + rq) <= wmarg);

    if (has && !ok) {
        if (L == 0) fallback_query(q, qx, qy, qz, cx, cy, cz, feats4, out);
        return;
    }
    if (!has) return;

    float acc[NF/4];
#pragma unroll
    for (int f = 0; f < NF/4; f++) acc[f] = 0.f;
    float wsum = 0.f;
#pragma unroll
    for (int t = 0; t < KNN; t++) {
        int p = (int)(gk[t] & IDXMASK);
        float4 g = __ldg(&g_winpos[cb + p]);
        int id = __ldg(&g_winid[cb + p]);
        float4 ic = __ldg(&g_icov_o[id]);
        float ddx = qx - g.x, ddy = qy - g.y, ddz = qz - g.z;
        float e2 = fmaf(ddx*ddx, ic.x, fmaf(ddy*ddy, ic.y, ddz*ddz*ic.z));
        float wgt = __expf(-0.5f * e2);
        wsum += wgt;
        const float4* fp = feats4 + (size_t)id * (NF/4) + L * 2;
        float4 f0 = __ldg(&fp[0]);
        float4 f1 = __ldg(&fp[1]);
        acc[0] = fmaf(wgt, f0.x, acc[0]);
        acc[1] = fmaf(wgt, f0.y, acc[1]);
        acc[2] = fmaf(wgt, f0.z, acc[2]);
        acc[3] = fmaf(wgt, f0.w, acc[3]);
        acc[4] = fmaf(wgt, f1.x, acc[4]);
        acc[5] = fmaf(wgt, f1.y, acc[5]);
        acc[6] = fmaf(wgt, f1.z, acc[6]);
        acc[7] = fmaf(wgt, f1.w, acc[7]);
    }
    float inv = 1.f / (wsum + 1e-8f);
    float4* o4 = (float4*)(out + (size_t)q * NF) + L * 2;
    o4[0] = make_float4(acc[0]*inv, acc[1]*inv, acc[2]*inv, acc[3]*inv);
    o4[1] = make_float4(acc[4]*inv, acc[5]*inv, acc[6]*inv, acc[7]*inv);
}

extern "C" void kernel_launch(void* const* d_in, const int* in_sizes, int n_in,
                              void* d_out, int out_size) {
    const float* coords = (const float*)d_in[0];
    const float* means  = (const float*)d_in[1];
    const float* logc   = (const float*)d_in[2];
    const float* feats  = (const float*)d_in[3];
    float* out = (float*)d_out;

    int M = in_sizes[0] / 3;
    int N = in_sizes[1] / 3;
    int mx = (M > N ? M : N);

    k_hist<<<(mx + 255) / 256, 256>>>(means, logc, N, coords, M);
    k_scatter<<<(mx + 255) / 256, 256>>>(means, N, M);
    k_window<<<NC, 256>>>();
    int qblocks = (M * 4 + 127) / 128;
    splash_q<<<qblocks, 128>>>(coords, (const float4*)feats, out, M);
}

// round 16
// speedup vs baseline: 1.8584x; 1.0554x over previous
#include <cuda_runtime.h>
#include <math.h>
#include <float.h>

#define G 8
#define NC (G*G*G)
#define MAXN 10016
#define MAXM 32768
#define KNN 16
#define NF 32
#define CAPW 512
#define WMAX 1024
#define NBKT 32
#define KD 12
#define IDXMASK 0x1FFu
#define CDMAX 0.1055f
#define BWIDTH (CDMAX / (float)NBKT)
#define INVBW ((float)NBKT / CDMAX)

// ---- device scratch (allocation-free) ----
__device__ float4 g_sorted[MAXN];
__device__ float4 g_icov_s[MAXN];
__device__ int g_cnt[NC], g_start[NC + 1];
__device__ int g_qcnt[NC], g_qstart[NC + 1];
__device__ int g_gcell[MAXN], g_grank[MAXN];
__device__ int g_qcell[MAXM], g_qrank[MAXM];
__device__ int g_qorder[MAXM];
__device__ int g_done;
__device__ float4 g_winpos[NC * CAPW + 32];
__device__ float4 g_winic[NC * CAPW + 32];
__device__ float  g_wincd[NC * CAPW + 32];
__device__ float  g_wmargin[NC];
__device__ int    g_nsw[NC];
__device__ int    g_nswp[NC];

__device__ __forceinline__ int cell_coord(float v) {
    int c = (int)(v * (float)G);
    return min(G - 1, max(0, c));
}

// 512-entry exclusive scan with 256 threads (2 entries/thread); zeroes src.
__device__ void scan512_zero(int* src, int* dst) {
    __shared__ int ws[8];
    int t = threadIdx.x, lane = t & 31, w = t >> 5;
    int c0 = src[2 * t], c1 = src[2 * t + 1];
    src[2 * t] = 0; src[2 * t + 1] = 0;
    int s = c0 + c1;
    int v = s;
    for (int o = 1; o < 32; o <<= 1) {
        int u = __shfl_up_sync(0xffffffffu, v, o);
        if (lane >= o) v += u;
    }
    if (lane == 31) ws[w] = v;
    __syncthreads();
    if (t < 32) {
        int p = (t < 8) ? ws[t] : 0;
        for (int o = 1; o < 8; o <<= 1) {
            int u = __shfl_up_sync(0xffffffffu, p, o);
            if (t >= o) p += u;
        }
        if (t < 8) ws[t] = p;
    }
    __syncthreads();
    int incl = v + (w ? ws[w - 1] : 0);
    int excl = incl - s;
    dst[2 * t + 1] = excl + c0;
    dst[2 * t + 2] = incl;
    if (t == 0) dst[0] = 0;
    __syncthreads();
}

// Histogram + (last finishing block) both scans. Fence-free: counters only
// mutated via atomicAdd-with-return (complete at L2); the scanning block's
// L1 never cached those lines (flushed at launch).
__global__ void k_hist(const float* __restrict__ means, int N,
                       const float* __restrict__ coords, int M) {
    int i = blockIdx.x * blockDim.x + threadIdx.x;
    if (i < N) {
        int c = (cell_coord(means[3*i+2]) * G + cell_coord(means[3*i+1])) * G
                + cell_coord(means[3*i+0]);
        g_gcell[i] = c;
        g_grank[i] = atomicAdd(&g_cnt[c], 1);
    }
    if (i < M) {
        int c = (cell_coord(coords[3*i+2]) * G + cell_coord(coords[3*i+1])) * G
                + cell_coord(coords[3*i+0]);
        g_qcell[i] = c;
        g_qrank[i] = atomicAdd(&g_qcnt[c], 1);
    }
    __syncthreads();
    __shared__ int is_last;
    if (threadIdx.x == 0) {
        int prev = atomicAdd(&g_done, 1);
        is_last = (prev == (int)gridDim.x - 1);
    }
    __syncthreads();
    if (!is_last) return;
    if (threadIdx.x == 0) g_done = 0;
    scan512_zero(g_cnt, g_start);
    scan512_zero(g_qcnt, g_qstart);
}

__global__ void k_scatter(const float* __restrict__ means,
                          const float* __restrict__ logc, int N, int M) {
    int i = blockIdx.x * blockDim.x + threadIdx.x;
    if (i < N) {
        int pos = g_start[g_gcell[i]] + g_grank[i];
        g_sorted[pos] = make_float4(means[3*i], means[3*i+1], means[3*i+2],
                                    __int_as_float(i));
        g_icov_s[pos] = make_float4(expf(-logc[3*i]), expf(-logc[3*i+1]),
                                    expf(-logc[3*i+2]), 0.f);
    }
    if (i < M) {
        int pos = g_qstart[g_qcell[i]] + g_qrank[i];
        g_qorder[pos] = i;
    }
}

// Per-cell radially-ordered window (bucket counting sort by center dist).
__global__ __launch_bounds__(256)
void k_window() {
    __shared__ float skey[WMAX];
    __shared__ int   sgid[WMAX];
    __shared__ int   cnt[NBKT], st[NBKT + 1], fil[NBKT];
    __shared__ int   rr0[9], roff[10], rcnt_s;

    const int cell = blockIdx.x, tid = threadIdx.x;
    const int cx = cell & 7, cy = (cell >> 3) & 7, cz = cell >> 6;
    const float ccx = (cx + 0.5f) * 0.125f;
    const float ccy = (cy + 0.5f) * 0.125f;
    const float ccz = (cz + 0.5f) * 0.125f;

    if (tid < NBKT) { cnt[tid] = 0; fil[tid] = 0; }

    const int x0 = max(cx - 1, 0), x1e = min(cx + 1, G - 1) + 1;
    if (tid == 0) {
        int rc = 0, n0 = 0;
        for (int z = max(cz - 1, 0); z <= min(cz + 1, G - 1); ++z) {
            for (int y = max(cy - 1, 0); y <= min(cy + 1, G - 1); ++y) {
                int base = (z * G + y) * G;
                int r0 = g_start[base + x0];
                int len = g_start[base + x1e] - r0;
                rr0[rc] = r0; roff[rc] = n0;
                n0 += len; rc++;
            }
        }
        roff[rc] = n0;
        rcnt_s = rc;
    }
    __syncthreads();

    const int rcnt = rcnt_s;
    const int n = roff[rcnt];
    const bool ovf = (n > WMAX);

    if (!ovf) {
        for (int i = tid; i < n; i += 256) {
            int k = 0;
#pragma unroll
            for (int kk = 1; kk < 9; kk++)
                if (kk < rcnt && i >= roff[kk]) k = kk;
            int src = rr0[k] + (i - roff[k]);
            float4 g = g_sorted[src];
            float dx = g.x - ccx, dy = g.y - ccy, dz = g.z - ccz;
            float cd = fmaf(dx, dx, fmaf(dy, dy, dz * dz));
            skey[i] = cd;
            sgid[i] = src;
            atomicAdd(&cnt[min(NBKT - 1, (int)(cd * INVBW))], 1);
        }
    }
    __syncthreads();

    if (tid < 32) {
        int v = cnt[tid];
        for (int o = 1; o < 32; o <<= 1) {
            int u = __shfl_up_sync(0xffffffffu, v, o);
            if (tid >= o) v += u;
        }
        st[tid + 1] = v;
        if (tid == 0) st[0] = 0;
    }
    __syncthreads();

    int nsw = min(n, CAPW);
    if (ovf) nsw = 0;
    const int nswp = min(CAPW, (nsw + 31) & ~31);

    if (tid == 0) {
        float marg = 1e30f;
        if (ovf) marg = -1.f;
        else if (n > CAPW) {
            int t = 0;
            while (t < NBKT && st[t + 1] <= CAPW) t++;
            marg = (float)t * BWIDTH;
        }
        g_wmargin[cell] = marg;
        g_nsw[cell] = nsw;
        g_nswp[cell] = nswp;
    }
    __syncthreads();

    if (!ovf) {
        for (int i = tid; i < n; i += 256) {
            float cd = skey[i];
            int b = min(NBKT - 1, (int)(cd * INVBW));
            int pos = st[b] + atomicAdd(&fil[b], 1);
            if (pos < CAPW) {
                int gi = sgid[i];
                float4 gp = g_sorted[gi];
                float m2 = fmaf(gp.x, gp.x, fmaf(gp.y, gp.y, gp.z * gp.z)) + 3.f;
                g_winpos[cell * CAPW + pos] = make_float4(gp.x, gp.y, gp.z, m2);
                float4 ic = g_icov_s[gi];
                g_winic[cell * CAPW + pos] = make_float4(ic.x, ic.y, ic.z, gp.w);
                g_wincd[cell * CAPW + pos] = cd;
            }
        }
        for (int i = nsw + tid; i < nswp; i += 256) {
            g_winpos[cell * CAPW + i] = make_float4(64.f, 64.f, 64.f,
                                                    3.f * 64.f * 64.f + 3.f);
            g_winic[cell * CAPW + i] = make_float4(0.f, 0.f, 0.f,
                                                   __int_as_float(0));
            g_wincd[cell * CAPW + i] = 1e30f;
        }
    }
}

// Exact per-query fallback (rare).
__device__ __noinline__ void fallback_query(int q, float qx, float qy, float qz,
                                            int cx, int cy, int cz,
                                            const float4* __restrict__ feats4,
                                            float* __restrict__ out) {
    const float h = 1.0f / (float)G;
    float bd[KNN];
#pragma unroll
    for (int t = 0; t < KNN; t++) bd[t] = FLT_MAX;

    int rfin = 1;
    for (int r = 1; r <= G; ++r) {
        rfin = r;
        for (int dz = -r; dz <= r; ++dz) {
            int z = cz + dz; if ((unsigned)z >= G) continue;
            for (int dy = -r; dy <= r; ++dy) {
                int y = cy + dy; if ((unsigned)y >= G) continue;
                bool edge = (dz == -r) | (dz == r) | (dy == -r) | (dy == r);
                int step = (r > 1 && !edge) ? 2 * r : 1;
                for (int dx = -r; dx <= r; dx += step) {
                    int x = cx + dx; if ((unsigned)x >= G) continue;
                    int cid = (z * G + y) * G + x;
                    int c0 = g_start[cid], c1 = g_start[cid + 1];
                    for (int c = c0; c < c1; ++c) {
                        float4 g = g_sorted[c];
                        float ddx = qx - g.x, ddy = qy - g.y, ddz = qz - g.z;
                        float d2 = fmaf(ddx, ddx, fmaf(ddy, ddy, ddz * ddz));
                        if (d2 < bd[0]) {
                            bd[0] = d2;
#pragma unroll
                            for (int t = 0; t < KNN - 1; t++) {
                                float a = fmaxf(bd[t], bd[t+1]);
                                float b = fminf(bd[t], bd[t+1]);
                                bd[t] = a; bd[t+1] = b;
                            }
                        }
                    }
                }
            }
        }
        float m = 1e30f;
        if (cx - r > 0)     m = fminf(m, qx - (float)(cx - r) * h);
        if (cx + r < G - 1) m = fminf(m, (float)(cx + r + 1) * h - qx);
        if (cy - r > 0)     m = fminf(m, qy - (float)(cy - r) * h);
        if (cy + r < G - 1) m = fminf(m, (float)(cy + r + 1) * h - qy);
        if (cz - r > 0)     m = fminf(m, qz - (float)(cz - r) * h);
        if (cz + r < G - 1) m = fminf(m, (float)(cz + r + 1) * h - qz);
        if (bd[0] <= m * m) break;
    }
    const float T = bd[0];

    int myp[KNN];
#pragma unroll
    for (int t = 0; t < KNN; t++) myp[t] = 0;
    int cnt = 0;
    {
        const int r = rfin;
        for (int dz = -r; dz <= r; ++dz) {
            int z = cz + dz; if ((unsigned)z >= G) continue;
            for (int dy = -r; dy <= r; ++dy) {
                int y = cy + dy; if ((unsigned)y >= G) continue;
                for (int dx = -r; dx <= r; ++dx) {
                    int x = cx + dx; if ((unsigned)x >= G) continue;
                    int cid = (z * G + y) * G + x;
                    int c0 = g_start[cid], c1 = g_start[cid + 1];
                    for (int c = c0; c < c1; ++c) {
                        float4 g = g_sorted[c];
                        float ddx = qx - g.x, ddy = qy - g.y, ddz = qz - g.z;
                        float d2 = fmaf(ddx, ddx, fmaf(ddy, ddy, ddz * ddz));
                        if (d2 <= T && cnt < KNN) { myp[cnt] = c; cnt++; }
                    }
                }
            }
        }
    }

    float acc[NF];
#pragma unroll
    for (int f = 0; f < NF; f++) acc[f] = 0.f;
    float wsum = 0.f;
#pragma unroll
    for (int t = 0; t < KNN; t++) {
        int p = myp[t];
        float4 g = g_sorted[p];
        float4 ic = g_icov_s[p];
        int id = __float_as_int(g.w);
        float ddx = qx - g.x, ddy = qy - g.y, ddz = qz - g.z;
        float e = fmaf(ddx*ddx, ic.x, fmaf(ddy*ddy, ic.y, ddz*ddz*ic.z));
        float wgt = __expf(-0.5f * e);
        wsum += wgt;
        const float4* fp = feats4 + (size_t)id * (NF/4);
#pragma unroll
        for (int cc = 0; cc < NF/4; cc++) {
            float4 fv = fp[cc];
            acc[4*cc+0] = fmaf(wgt, fv.x, acc[4*cc+0]);
            acc[4*cc+1] = fmaf(wgt, fv.y, acc[4*cc+1]);
            acc[4*cc+2] = fmaf(wgt, fv.z, acc[4*cc+2]);
            acc[4*cc+3] = fmaf(wgt, fv.w, acc[4*cc+3]);
        }
    }
    float inv = 1.f / (wsum + 1e-8f);
    float4* o4 = (float4*)(out + (size_t)q * NF);
#pragma unroll
    for (int cc = 0; cc < NF/4; cc++)
        o4[cc] = make_float4(acc[4*cc+0]*inv, acc[4*cc+1]*inv,
                             acc[4*cc+2]*inv, acc[4*cc+3]*inv);
}

// Main: 4 lanes/query, 8 queries/warp, padded windows, prefetched early exit
// with quad-tight d16 bound (union of each lane's 4 smallest => d16 <=
// quad_max(key[8])).
__global__ __launch_bounds__(128, 7)
void splash_q(const float* __restrict__ coords,
              const float4* __restrict__ feats4,
              float* __restrict__ out, int M) {
    const int gw = (blockIdx.x * blockDim.x + threadIdx.x) >> 5;
    const int lane = threadIdx.x & 31;
    const int L = lane & 3;
    const int qslot = gw * 8 + (lane >> 2);
    const bool has = qslot < M;

    const int q = g_qorder[has ? qslot : 0];
    const float qx = coords[3*q+0], qy = coords[3*q+1], qz = coords[3*q+2];
    const int cx = cell_coord(qx), cy = cell_coord(qy), cz = cell_coord(qz);
    const int cell = (cz * G + cy) * G + cx;
    const int cb = cell * CAPW;
    const int nSW = g_nsw[cell];
    const int nSWP = g_nswp[cell];
    const float wmarg = g_wmargin[cell];

    const float qq = fmaf(qx, qx, fmaf(qy, qy, qz * qz));
    const float n2x = -2.f * qx, n2y = -2.f * qy, n2z = -2.f * qz;
    const float ccx = (cx + 0.5f) * 0.125f;
    const float ccy = (cy + 0.5f) * 0.125f;
    const float ccz = (cz + 0.5f) * 0.125f;
    float rdx = qx - ccx, rdy = qy - ccy, rdz = qz - ccz;
    const float rq = sqrtf(fmaf(rdx, rdx, fmaf(rdy, rdy, rdz * rdz)));

    const bool mainable = has && nSW >= 32 && wmarg >= 0.f;

    unsigned key[KD];
#pragma unroll
    for (int t = 0; t < KD; t++) key[t] = 0xFFFFFFFFu;

    bool done = !mainable;
    for (int base = 0; !__all_sync(0xffffffffu, done); base += 32) {
        if (!done) {
            // Prefetch next chunk's exit key; overlaps candidate loads.
            float ncd = __ldg(&g_wincd[cb + base + 32]);
            float tv[8];
#pragma unroll
            for (int k = 0; k < 8; k++) {
                float4 g = __ldg(&g_winpos[cb + base + L + 4 * k]);
                tv[k] = fmaf(g.x, n2x, fmaf(g.y, n2y, fmaf(g.z, n2z, g.w)));
            }
#pragma unroll
            for (int k = 0; k < 8; k++) {
                int j = base + L + 4 * k;
                unsigned kn = (__float_as_uint(tv[k]) & ~IDXMASK) | (unsigned)j;
                if (kn < key[0]) {
                    key[0] = kn;
#pragma unroll
                    for (int s = 0; s < KD - 1; s++) {
                        unsigned a = umax(key[s], key[s+1]);
                        unsigned b = umin(key[s], key[s+1]);
                        key[s] = a; key[s+1] = b;
                    }
                }
            }
            if (base + 32 >= nSWP) done = true;
            else {
                // Quad-tight bound: each lane's 4 smallest kept are
                // key[8..11]; union over quad = 16 values all <= kb.
                // Unfilled lanes give sentinel -> NaN -> no exit.
                unsigned am = __activemask();
                unsigned kb = key[8];
                kb = umax(kb, __shfl_xor_sync(am, kb, 1));
                kb = umax(kb, __shfl_xor_sync(am, kb, 2));
                float d16sq = __uint_as_float(kb & ~IDXMASK) - 3.f + qq;
                if (d16sq >= 0.f) {
                    float dn = sqrtf(d16sq) + rq;
                    if (ncd - BWIDTH > dn * dn) done = true;
                }
            }
        }
    }

    // Two-stage exact quad merge (pads inlined: slots 0..3 are +inf).
#define PK_(i) ((i) < 4 ? 0xFFFFFFFFu : key[(i) - 4])
    unsigned e[16];
#pragma unroll
    for (int t = 0; t < 16; t++) {
        unsigned pp = __shfl_xor_sync(0xffffffffu, PK_(15 - t), 1);
        e[t] = umin(PK_(t), pp);
    }
#undef PK_
#define CE_(i, j) { unsigned a_ = umax(e[i], e[j]); unsigned b_ = umin(e[i], e[j]); e[i] = a_; e[j] = b_; }
#pragma unroll
    for (int i = 0; i < 8; i++) CE_(i, i + 8);
#pragma unroll
    for (int hb = 0; hb < 16; hb += 8)
#pragma unroll
        for (int i = 0; i < 4; i++) CE_(hb + i, hb + i + 4);
#pragma unroll
    for (int hb = 0; hb < 16; hb += 4)
#pragma unroll
        for (int i = 0; i < 2; i++) CE_(hb + i, hb + i + 2);
#pragma unroll
    for (int i = 0; i < 16; i += 2) CE_(i, i + 1);
#undef CE_

    unsigned gk[16];
#pragma unroll
    for (int t = 0; t < 16; t++) {
        unsigned pp = __shfl_xor_sync(0xffffffffu, e[15 - t], 2);
        gk[t] = umin(e[t], pp);
    }
    unsigned mx = gk[0];
#pragma unroll
    for (int t = 1; t < 16; t++) mx = umax(mx, gk[t]);

    bool lane_ok = (key[0] >= mx);
    unsigned bal = __ballot_sync(0xffffffffu, lane_ok);
    bool quad_ok = (((bal >> (lane & ~3)) & 0xFu) == 0xFu);

    float d16sq = __uint_as_float(mx & ~IDXMASK) - 3.f + qq;
    const float h = 0.125f;
    float m = 1e30f;
    if (cx - 1 > 0)     m = fminf(m, qx - (float)(cx - 1) * h);
    if (cx + 1 < G - 1) m = fminf(m, (float)(cx + 2) * h - qx);
    if (cy - 1 > 0)     m = fminf(m, qy - (float)(cy - 1) * h);
    if (cy + 1 < G - 1) m = fminf(m, (float)(cy + 2) * h - qy);
    if (cz - 1 > 0)     m = fminf(m, qz - (float)(cz - 1) * h);
    if (cz + 1 < G - 1) m = fminf(m, (float)(cz + 2) * h - qz);

    float d16c = sqrtf(fmaxf(d16sq, 0.f));
    bool ok = mainable && quad_ok && (d16sq <= m * m)
              && ((d16c + rq) * (d16c + rq) <= wmarg);

    if (has && !ok) {
        if (L == 0) fallback_query(q, qx, qy, qz, cx, cy, cz, feats4, out);
        return;
    }
    if (!has) return;

    float acc[NF/4];
#pragma unroll
    for (int f = 0; f < NF/4; f++) acc[f] = 0.f;
    float wsum = 0.f;
#pragma unroll
    for (int t = 0; t < KNN; t++) {
        int p = (int)(gk[t] & IDXMASK);
        float4 g = __ldg(&g_winpos[cb + p]);
        float4 ic = __ldg(&g_winic[cb + p]);
        int id = __float_as_int(ic.w);
        float ddx = qx - g.x, ddy = qy - g.y, ddz = qz - g.z;
        float e2 = fmaf(ddx*ddx, ic.x, fmaf(ddy*ddy, ic.y, ddz*ddz*ic.z));
        float wgt = __expf(-0.5f * e2);
        wsum += wgt;
        const float4* fp = feats4 + (size_t)id * (NF/4) + L * 2;
        float4 f0 = __ldg(&fp[0]);
        float4 f1 = __ldg(&fp[1]);
        acc[0] = fmaf(wgt, f0.x, acc[0]);
        acc[1] = fmaf(wgt, f0.y, acc[1]);
        acc[2] = fmaf(wgt, f0.z, acc[2]);
        acc[3] = fmaf(wgt, f0.w, acc[3]);
        acc[4] = fmaf(wgt, f1.x, acc[4]);
        acc[5] = fmaf(wgt, f1.y, acc[5]);
        acc[6] = fmaf(wgt, f1.z, acc[6]);
        acc[7] = fmaf(wgt, f1.w, acc[7]);
    }
    float inv = 1.f / (wsum + 1e-8f);
    float4* o4 = (float4*)(out + (size_t)q * NF) + L * 2;
    o4[0] = make_float4(acc[0]*inv, acc[1]*inv, acc[2]*inv, acc[3]*inv);
    o4[1] = make_float4(acc[4]*inv, acc[5]*inv, acc[6]*inv, acc[7]*inv);
}

extern "C" void kernel_launch(void* const* d_in, const int* in_sizes, int n_in,
                              void* d_out, int out_size) {
    const float* coords = (const float*)d_in[0];
    const float* means  = (const float*)d_in[1];
    const float* logc   = (const float*)d_in[2];
    const float* feats  = (const float*)d_in[3];
    float* out = (float*)d_out;

    int M = in_sizes[0] / 3;
    int N = in_sizes[1] / 3;
    int mx = (M > N ? M : N);

    k_hist<<<(mx + 255) / 256, 256>>>(means, N, coords, M);
    k_scatter<<<(mx + 255) / 256, 256>>>(means, logc, N, M);
    k_window<<<NC, 256>>>();
    int qblocks = (M * 4 + 127) / 128;
    splash_q<<<qblocks, 128>>>(coords, (const float4*)feats, out, M);
}